// round 14
// baseline (speedup 1.0000x reference)
#include <cuda_runtime.h>
#include <cuda_bf16.h>
#include <math.h>
#include <stdint.h>

// ---------------- problem constants ----------------
#define BB   2
#define SS   2048
#define DD   1024
#define HH   16
#define DHH  64
#define MLPD 4096
#define ROWS (BB*SS)          // 4096 tokens
#define CCH  128              // attention chunk length
#define NCH  (SS/CCH)         // 16 chunks per sequence
#define BHN  (BB*HH)          // 32 (b,h) pairs
#define NCHUNKS_TOT (BHN*NCH) // 512

typedef __nv_bfloat16 bf16;

// ---------------- scratch (device globals; no allocation allowed) ----------------
__device__ float g_q   [ROWS*DD];
__device__ float g_k   [ROWS*DD];
__device__ float g_v   [ROWS*DD];
__device__ float g_x2  [ROWS*DD];
__device__ bf16 g_xh[ROWS*DD],  g_xl[ROWS*DD];
__device__ bf16 g_ah[ROWS*DD],  g_al[ROWS*DD];
__device__ bf16 g_yh[ROWS*DD],  g_yl[ROWS*DD];
__device__ bf16 g_h1h[ROWS*MLPD], g_h1l[ROWS*MLPD];
// transposed split weights
__device__ bf16 g_wqkvt_h[3*DD*DD], g_wqkvt_l[3*DD*DD];   // q|k|v segments
__device__ bf16 g_wot_h[DD*DD],  g_wot_l[DD*DD];
__device__ bf16 g_w1t_h[DD*MLPD], g_w1t_l[DD*MLPD];
__device__ bf16 g_w2t_h[MLPD*DD], g_w2t_l[MLPD*DD];
// attention scratch
__device__ float g_ckv  [NCHUNKS_TOT*DHH*DHH];
__device__ float g_cks  [NCHUNKS_TOT*DHH];
__device__ float g_kvpre[NCHUNKS_TOT*DHH*DHH];
__device__ float g_kspre[NCHUNKS_TOT*DHH];

// ---------------- helpers ----------------
__device__ __forceinline__ float gelu_t(float x) {
    float x3 = x * x * x;
    float t = tanhf(0.7978845608028654f * (x + 0.044715f * x3));
    return 0.5f * x * (1.0f + t);
}
__device__ __forceinline__ unsigned pkbf(float a, float b) {
    __nv_bfloat162 t = __floats2bfloat162_rn(a, b);
    return *reinterpret_cast<unsigned*>(&t);
}
__device__ __forceinline__ uint32_t s2u(const void* p) {
    return (uint32_t)__cvta_generic_to_shared(p);
}
__device__ __forceinline__ void cpa16(uint32_t s, const void* g) {
    asm volatile("cp.async.cg.shared.global [%0], [%1], 16;" :: "r"(s), "l"(g));
}
#define CPA_COMMIT() asm volatile("cp.async.commit_group;" ::: "memory")
#define CPA_WAIT0()  asm volatile("cp.async.wait_group 0;" ::: "memory")

__device__ __forceinline__ void ldsm4(uint32_t& r0, uint32_t& r1, uint32_t& r2,
                                      uint32_t& r3, uint32_t a) {
    asm volatile("ldmatrix.sync.aligned.m8n8.x4.shared.b16 {%0,%1,%2,%3}, [%4];"
                 : "=r"(r0), "=r"(r1), "=r"(r2), "=r"(r3) : "r"(a));
}
__device__ __forceinline__ void ldsm2(uint32_t& r0, uint32_t& r1, uint32_t a) {
    asm volatile("ldmatrix.sync.aligned.m8n8.x2.shared.b16 {%0,%1}, [%2];"
                 : "=r"(r0), "=r"(r1) : "r"(a));
}
__device__ __forceinline__ void hmma(float* c, const uint32_t* a, const uint32_t* b) {
    asm volatile(
        "mma.sync.aligned.m16n8k16.row.col.f32.bf16.bf16.f32 "
        "{%0,%1,%2,%3}, {%4,%5,%6,%7}, {%8,%9}, {%0,%1,%2,%3};"
        : "+f"(c[0]), "+f"(c[1]), "+f"(c[2]), "+f"(c[3])
        : "r"(a[0]), "r"(a[1]), "r"(a[2]), "r"(a[3]), "r"(b[0]), "r"(b[1]));
}

// ---------------- fused weight transpose + bf16 split (single launch) ----------------
__global__ void __launch_bounds__(256)
wsplit_all(const float* __restrict__ wq, const float* __restrict__ wk,
           const float* __restrict__ wv, const float* __restrict__ wo,
           const float* __restrict__ w1, const float* __restrict__ w2)
{
    int id = blockIdx.x;
    const float* W;
    bf16 *Th, *Tl;
    int K, N, n0, k0;
    if (id < 3072) {
        int w = id >> 10, tile = id & 1023;
        W = (w == 0) ? wq : (w == 1) ? wk : wv;
        K = DD; N = DD;
        Th = g_wqkvt_h + (size_t)w * DD * DD;
        Tl = g_wqkvt_l + (size_t)w * DD * DD;
        n0 = (tile & 31) * 32; k0 = (tile >> 5) * 32;
    } else if (id < 4096) {
        int tile = id - 3072;
        W = wo; K = DD; N = DD;
        Th = g_wot_h; Tl = g_wot_l;
        n0 = (tile & 31) * 32; k0 = (tile >> 5) * 32;
    } else if (id < 8192) {
        int tile = id - 4096;
        W = w1; K = DD; N = MLPD;
        Th = g_w1t_h; Tl = g_w1t_l;
        n0 = (tile & 127) * 32; k0 = (tile >> 7) * 32;
    } else {
        int tile = id - 8192;
        W = w2; K = MLPD; N = DD;
        Th = g_w2t_h; Tl = g_w2t_l;
        n0 = (tile & 31) * 32; k0 = (tile >> 5) * 32;
    }

    __shared__ float t[32][33];
    int tx = threadIdx.x & 31, ty = threadIdx.x >> 5;
#pragma unroll
    for (int r = 0; r < 4; r++) {
        int k = k0 + ty + r * 8;
        t[ty + r * 8][tx] = W[(size_t)k * N + n0 + tx];
    }
    __syncthreads();
#pragma unroll
    for (int r = 0; r < 4; r++) {
        int n = n0 + ty + r * 8;
        float vv = t[tx][ty + r * 8];
        bf16 h = __float2bfloat16_rn(vv);
        Th[(size_t)n * K + k0 + tx] = h;
        Tl[(size_t)n * K + k0 + tx] = __float2bfloat16_rn(vv - __bfloat162float(h));
    }
}

// ---------------- LayerNorm -> split bf16 ----------------
__global__ void __launch_bounds__(256)
ln_kernel(const float* __restrict__ x, const float* __restrict__ sc,
          const float* __restrict__ bi, bf16* __restrict__ yh, bf16* __restrict__ yl)
{
    int row = blockIdx.x;
    int t = threadIdx.x;
    const float4* xr = (const float4*)(x + (size_t)row * DD);
    float4 v = xr[t];
    float s  = v.x + v.y + v.z + v.w;
    float ss = v.x*v.x + v.y*v.y + v.z*v.z + v.w*v.w;
#pragma unroll
    for (int o = 16; o > 0; o >>= 1) {
        s  += __shfl_xor_sync(0xffffffffu, s,  o);
        ss += __shfl_xor_sync(0xffffffffu, ss, o);
    }
    __shared__ float sh[16];
    int w = t >> 5, l = t & 31;
    if (l == 0) { sh[w] = s; sh[8 + w] = ss; }
    __syncthreads();
    if (t < 32) {
        s  = (t < 8) ? sh[t]     : 0.f;
        ss = (t < 8) ? sh[8 + t] : 0.f;
#pragma unroll
        for (int o = 4; o > 0; o >>= 1) {
            s  += __shfl_xor_sync(0xffffffffu, s,  o);
            ss += __shfl_xor_sync(0xffffffffu, ss, o);
        }
        if (t == 0) { sh[0] = s; sh[8] = ss; }
    }
    __syncthreads();
    float mean = sh[0] * (1.0f / (float)DD);
    float var  = sh[8] * (1.0f / (float)DD) - mean * mean;
    float rs = rsqrtf(var + 1e-6f);
    float4 scv = ((const float4*)sc)[t];
    float4 biv = ((const float4*)bi)[t];
    float o0 = (v.x - mean) * rs * scv.x + biv.x;
    float o1 = (v.y - mean) * rs * scv.y + biv.y;
    float o2 = (v.z - mean) * rs * scv.z + biv.z;
    float o3 = (v.w - mean) * rs * scv.w + biv.w;
    float h0 = __bfloat162float(__float2bfloat16_rn(o0));
    float h1 = __bfloat162float(__float2bfloat16_rn(o1));
    float h2 = __bfloat162float(__float2bfloat16_rn(o2));
    float h3 = __bfloat162float(__float2bfloat16_rn(o3));
    size_t base = (size_t)row * DD + t * 4;
    *(uint2*)(yh + base) = make_uint2(pkbf(h0, h1), pkbf(h2, h3));
    *(uint2*)(yl + base) = make_uint2(pkbf(o0 - h0, o1 - h1), pkbf(o2 - h2, o3 - h3));
}

// ---------------- mma.sync split-bf16 GEMM ----------------
// CTA tile 128x128, 128 threads (4 warps, 2x2 grid), warp tile 64x64, BK=32, 2-stage.
// EPI: 0 plain fp32 ; 1 relu+eps fp32 ; 2 +res fp32 ; 3 +bias gelu -> split bf16 ;
//      4 +bias +res fp32 ; 5 fused QKV (seg = gcol>>10: 0,1 relu+eps ; 2 plain)
#define BKK        32
#define ROWSTRIDE  40                      // bf16 elems per smem row (80B)
#define MAT_B      (128*ROWSTRIDE*2)       // 10240 bytes per matrix per stage
#define STAGE_B    (4*MAT_B)               // 40960 bytes per stage
#define GEMM_SMEM_BYTES (2*STAGE_B)        // 81920

template <int EPI>
__global__ void __launch_bounds__(128)
mma_gemm(const bf16* __restrict__ Ah, const bf16* __restrict__ Al,
         const bf16* __restrict__ Bh, const bf16* __restrict__ Bl,
         float* __restrict__ C, float* __restrict__ C2, float* __restrict__ C3,
         bf16* __restrict__ Ch, bf16* __restrict__ Cl,
         const float* __restrict__ bias, const float* __restrict__ res,
         int M, int N, int K)
{
    extern __shared__ bf16 smbuf[];
    uint32_t sb = s2u(smbuf);
    int tid = threadIdx.x, lane = tid & 31, wid = tid >> 5;
    int wm = wid >> 1, wn = wid & 1;              // 2 x 2 warp grid, 64x64 tiles
    int m0 = blockIdx.y * 128, n0 = blockIdx.x * 128;

    float acc[4][8][4];
#pragma unroll
    for (int f = 0; f < 4; f++)
#pragma unroll
        for (int g = 0; g < 8; g++)
#pragma unroll
            for (int e = 0; e < 4; e++) acc[f][g][e] = 0.f;

    auto load_stage = [&](int kt, int st) {
        int koff = kt * BKK;
        uint32_t s0 = sb + (uint32_t)st * STAGE_B;
#pragma unroll
        for (int r = 0; r < 4; r++) {
            int e = tid + 128 * r;                // 0..511
            int row = e >> 2, q = e & 3;
            uint32_t so = (uint32_t)(row * ROWSTRIDE + q * 8) * 2;
            size_t ga = (size_t)(m0 + row) * K + koff + q * 8;
            size_t gb = (size_t)(n0 + row) * K + koff + q * 8;
            cpa16(s0 + 0 * MAT_B + so, Ah + ga);
            cpa16(s0 + 1 * MAT_B + so, Al + ga);
            cpa16(s0 + 2 * MAT_B + so, Bh + gb);
            cpa16(s0 + 3 * MAT_B + so, Bl + gb);
        }
    };

    load_stage(0, 0);
    CPA_COMMIT();
    CPA_WAIT0();
    __syncthreads();

    const int KT = K / BKK;
    for (int kt = 0; kt < KT; ++kt) {
        int st = kt & 1;
        if (kt + 1 < KT) { load_stage(kt + 1, st ^ 1); CPA_COMMIT(); }

        uint32_t sA = sb + (uint32_t)st * STAGE_B;
        uint32_t sB = sA + 2 * MAT_B;
#pragma unroll
        for (int ks = 0; ks < 2; ++ks) {
            int kb = ks * 16;
            uint32_t ah[4][4], al[4][4], bh[8][2], bl[8][2];
#pragma unroll
            for (int f = 0; f < 4; f++) {
                int row = wm * 64 + f * 16 + (lane & 7) + ((lane >> 3) & 1) * 8;
                int col = kb + ((lane >> 4) << 3);
                uint32_t ad = sA + (uint32_t)(row * ROWSTRIDE + col) * 2;
                ldsm4(ah[f][0], ah[f][1], ah[f][2], ah[f][3], ad);
                ldsm4(al[f][0], al[f][1], al[f][2], al[f][3], ad + MAT_B);
            }
#pragma unroll
            for (int g = 0; g < 8; g++) {
                int l2 = lane & 15;
                int nrow = wn * 64 + g * 8 + (l2 & 7);
                int col = kb + ((l2 >> 3) << 3);
                uint32_t bd = sB + (uint32_t)(nrow * ROWSTRIDE + col) * 2;
                ldsm2(bh[g][0], bh[g][1], bd);
                ldsm2(bl[g][0], bl[g][1], bd + MAT_B);
            }
#pragma unroll
            for (int f = 0; f < 4; f++)
#pragma unroll
                for (int g = 0; g < 8; g++) hmma(acc[f][g], ah[f], bh[g]);
#pragma unroll
            for (int f = 0; f < 4; f++)
#pragma unroll
                for (int g = 0; g < 8; g++) hmma(acc[f][g], ah[f], bl[g]);
#pragma unroll
            for (int f = 0; f < 4; f++)
#pragma unroll
                for (int g = 0; g < 8; g++) hmma(acc[f][g], al[f], bh[g]);
        }
        if (kt + 1 < KT) CPA_WAIT0();
        __syncthreads();
    }

    // ---- epilogue: regs -> smem float stage -> coalesced global stores ----
    float* stg = (float*)smbuf;                   // 128 x 132 floats = 67584 B
#pragma unroll
    for (int f = 0; f < 4; f++) {
        int mrow = wm * 64 + f * 16 + (lane >> 2);
#pragma unroll
        for (int g = 0; g < 8; g++) {
            int ncol = wn * 64 + g * 8 + (lane & 3) * 2;
            stg[(mrow    ) * 132 + ncol    ] = acc[f][g][0];
            stg[(mrow    ) * 132 + ncol + 1] = acc[f][g][1];
            stg[(mrow + 8) * 132 + ncol    ] = acc[f][g][2];
            stg[(mrow + 8) * 132 + ncol + 1] = acc[f][g][3];
        }
    }
    __syncthreads();

#pragma unroll
    for (int r = 0; r < 32; r++) {
        int e = tid + 128 * r;                    // 0..4095 float4s
        int row = e >> 5, q = e & 31;
        float4 o = *(float4*)&stg[row * 132 + q * 4];
        int grow = m0 + row, gcol = n0 + q * 4;
        size_t gi = (size_t)grow * N + gcol;

        if (EPI == 0) {
            *(float4*)(C + gi) = o;
        } else if (EPI == 1) {
            o.x = fmaxf(o.x, 0.f) + 1e-3f;
            o.y = fmaxf(o.y, 0.f) + 1e-3f;
            o.z = fmaxf(o.z, 0.f) + 1e-3f;
            o.w = fmaxf(o.w, 0.f) + 1e-3f;
            *(float4*)(C + gi) = o;
        } else if (EPI == 2) {
            float4 rr = *(const float4*)(res + gi);
            o.x += rr.x; o.y += rr.y; o.z += rr.z; o.w += rr.w;
            *(float4*)(C + gi) = o;
        } else if (EPI == 3) {
            float4 bb = *(const float4*)(bias + gcol);
            o.x = gelu_t(o.x + bb.x); o.y = gelu_t(o.y + bb.y);
            o.z = gelu_t(o.z + bb.z); o.w = gelu_t(o.w + bb.w);
            float h0 = __bfloat162float(__float2bfloat16_rn(o.x));
            float h1 = __bfloat162float(__float2bfloat16_rn(o.y));
            float h2 = __bfloat162float(__float2bfloat16_rn(o.z));
            float h3 = __bfloat162float(__float2bfloat16_rn(o.w));
            *(uint2*)(Ch + gi) = make_uint2(pkbf(h0, h1), pkbf(h2, h3));
            *(uint2*)(Cl + gi) = make_uint2(pkbf(o.x - h0, o.y - h1), pkbf(o.z - h2, o.w - h3));
        } else if (EPI == 4) {
            float4 bb = *(const float4*)(bias + gcol);
            float4 rr = *(const float4*)(res + gi);
            o.x += bb.x + rr.x; o.y += bb.y + rr.y;
            o.z += bb.z + rr.z; o.w += bb.w + rr.w;
            *(float4*)(C + gi) = o;
        } else {  // EPI == 5: fused QKV
            int seg = gcol >> 10;
            int cin = gcol & 1023;
            float* dst = (seg == 0) ? C : (seg == 1) ? C2 : C3;
            if (seg < 2) {
                o.x = fmaxf(o.x, 0.f) + 1e-3f;
                o.y = fmaxf(o.y, 0.f) + 1e-3f;
                o.z = fmaxf(o.z, 0.f) + 1e-3f;
                o.w = fmaxf(o.w, 0.f) + 1e-3f;
            }
            *(float4*)(dst + (size_t)grow * DD + cin) = o;
        }
    }
}

// ---------------- attention pass A: per-chunk KV = phiK^T V and ksum ----------------
__global__ void __launch_bounds__(512)
attn_chunk_kernel(const float* __restrict__ Kk, const float* __restrict__ V,
                  float* __restrict__ ckv, float* __restrict__ cks)
{
    __shared__ float sK[64][64];
    __shared__ float sV[64][64];
    int g = blockIdx.x;
    int c = g & 15, bh = g >> 4;
    int h = bh & 15, b = bh >> 4;
    int row0 = b * SS + c * CCH;
    int colBase = h * 64;
    int t = threadIdx.x;
    int m = t >> 3;
    int d0 = (t & 7) * 8;

    float acc[8];
#pragma unroll
    for (int w = 0; w < 8; w++) acc[w] = 0.f;
    float ks = 0.f;

    for (int half = 0; half < 2; ++half) {
#pragma unroll
        for (int r = 0; r < 8; r++) {
            int e = t + 512 * r;
            int s = e >> 6, d = e & 63;
            size_t gi = (size_t)(row0 + half * 64 + s) * DD + colBase + d;
            sK[s][d] = Kk[gi];
            sV[s][d] = V[gi];
        }
        __syncthreads();
#pragma unroll 4
        for (int s = 0; s < 64; s++) {
            float kk = sK[s][m];
            if ((t & 7) == 0) ks += kk;
            const float* vr = &sV[s][d0];
            float4 v0 = *(const float4*)vr;
            float4 v1 = *(const float4*)(vr + 4);
            acc[0] += kk * v0.x; acc[1] += kk * v0.y;
            acc[2] += kk * v0.z; acc[3] += kk * v0.w;
            acc[4] += kk * v1.x; acc[5] += kk * v1.y;
            acc[6] += kk * v1.z; acc[7] += kk * v1.w;
        }
        __syncthreads();
    }
    float* op = ckv + (size_t)g * (DHH * DHH) + m * 64 + d0;
    *(float4*)op       = make_float4(acc[0], acc[1], acc[2], acc[3]);
    *(float4*)(op + 4) = make_float4(acc[4], acc[5], acc[6], acc[7]);
    if ((t & 7) == 0) cks[g * 64 + m] = ks;
}

// ---------------- attention pass B: parallel exclusive prefix (gather form) ----------------
__global__ void __launch_bounds__(256)
attn_pre_kernel(const float* __restrict__ ckv, const float* __restrict__ cks,
                float* __restrict__ kvpre, float* __restrict__ kspre)
{
    int g = blockIdx.x;
    int c = g & 15, bh = g >> 4;
    int t = threadIdx.x;
    float run[16];
#pragma unroll
    for (int r = 0; r < 16; r++) run[r] = 0.f;
    for (int cc = 0; cc < c; cc++) {
        const float* p = ckv + ((size_t)(bh * NCH + cc)) * (DHH * DHH);
#pragma unroll
        for (int r = 0; r < 16; r++) run[r] += p[t + 256 * r];
    }
    float* o = kvpre + (size_t)g * (DHH * DHH);
#pragma unroll
    for (int r = 0; r < 16; r++) o[t + 256 * r] = run[r];
    if (t < 64) {
        float kr = 0.f;
        for (int cc = 0; cc < c; cc++) kr += cks[(bh * NCH + cc) * 64 + t];
        kspre[g * 64 + t] = kr;
    }
}

// ---------------- attention pass C: per-chunk causal output -> split bf16 ----------------
#define ATTN_SMEM_FLOATS (64*132 + 64*132 + 128*68 + 64*68 + 64 + 128*132)
#define ATTN_SMEM_BYTES  (ATTN_SMEM_FLOATS * 4)

__global__ void __launch_bounds__(256)
attn_out_kernel(const float* __restrict__ Q, const float* __restrict__ Kk,
                const float* __restrict__ V, const float* __restrict__ kvpre,
                const float* __restrict__ kspre,
                bf16* __restrict__ ah, bf16* __restrict__ al)
{
    extern __shared__ float sm[];
    float* sQt = sm;
    float* sKt = sQt + 64 * 132;
    float* sV  = sKt + 64 * 132;
    float* sKV = sV  + 128 * 68;
    float* sKs = sKV + 64 * 68;
    float* sA  = sKs + 64;

    int g = blockIdx.x;
    int c = g & 15, bh = g >> 4;
    int h = bh & 15, b = bh >> 4;
    int row0 = b * SS + c * CCH;
    int colBase = h * 64;
    int t = threadIdx.x;

#pragma unroll
    for (int r = 0; r < 32; r++) {
        int e = t + 256 * r;
        int s = e >> 6, m = e & 63;
        size_t gi = (size_t)(row0 + s) * DD + colBase + m;
        sQt[m * 132 + s] = Q[gi];
        sKt[m * 132 + s] = Kk[gi];
        sV[s * 68 + m]   = V[gi];
    }
#pragma unroll
    for (int r = 0; r < 16; r++) {
        int e = t + 256 * r;
        sKV[(e >> 6) * 68 + (e & 63)] = kvpre[(size_t)g * (DHH * DHH) + e];
    }
    if (t < 64) sKs[t] = kspre[g * 64 + t];
    __syncthreads();

    {
        int ty = t >> 4, tx = t & 15;
        float accA[8][8];
#pragma unroll
        for (int i = 0; i < 8; i++)
#pragma unroll
            for (int j = 0; j < 8; j++) accA[i][j] = 0.f;
        for (int kk = 0; kk < 64; kk++) {
            const float* qr = &sQt[kk * 132 + ty * 8];
            float4 q0 = *(const float4*)qr;
            float4 q1 = *(const float4*)(qr + 4);
            const float* kr = &sKt[kk * 132 + tx * 8];
            float4 k0 = *(const float4*)kr;
            float4 k1 = *(const float4*)(kr + 4);
            float qa[8] = { q0.x, q0.y, q0.z, q0.w, q1.x, q1.y, q1.z, q1.w };
            float kb[8] = { k0.x, k0.y, k0.z, k0.w, k1.x, k1.y, k1.z, k1.w };
#pragma unroll
            for (int i = 0; i < 8; i++)
#pragma unroll
                for (int j = 0; j < 8; j++) accA[i][j] += qa[i] * kb[j];
        }
        int i0 = ty * 8, j0 = tx * 8;
#pragma unroll
        for (int i = 0; i < 8; i++)
#pragma unroll
            for (int j = 0; j < 8; j++)
                sA[(i0 + i) * 132 + (j0 + j)] = (j0 + j <= i0 + i) ? accA[i][j] : 0.f;
    }
    __syncthreads();

    {
        int i = t >> 1;
        int d0 = (t & 1) * 32;
        float acc[32];
#pragma unroll
        for (int w = 0; w < 32; w++) acc[w] = 0.f;
        float den = 0.f;
        for (int j = 0; j < 128; j++) {
            float a = sA[i * 132 + j];
            den += a;
            const float* vr = &sV[j * 68 + d0];
#pragma unroll
            for (int w = 0; w < 8; w++) {
                float4 vv = *(const float4*)(vr + 4 * w);
                acc[4 * w + 0] += a * vv.x;
                acc[4 * w + 1] += a * vv.y;
                acc[4 * w + 2] += a * vv.z;
                acc[4 * w + 3] += a * vv.w;
            }
        }
        for (int m = 0; m < 64; m++) {
            float p = sQt[m * 132 + i];
            den += p * sKs[m];
            const float* kr = &sKV[m * 68 + d0];
#pragma unroll
            for (int w = 0; w < 8; w++) {
                float4 vv = *(const float4*)(kr + 4 * w);
                acc[4 * w + 0] += p * vv.x;
                acc[4 * w + 1] += p * vv.y;
                acc[4 * w + 2] += p * vv.z;
                acc[4 * w + 3] += p * vv.w;
            }
        }
        float inv = 1.0f / den;
        size_t base = (size_t)(row0 + i) * DD + colBase + d0;
#pragma unroll
        for (int w = 0; w < 8; w++) {
            float o0 = acc[4*w+0] * inv, o1 = acc[4*w+1] * inv;
            float o2 = acc[4*w+2] * inv, o3 = acc[4*w+3] * inv;
            float h0 = __bfloat162float(__float2bfloat16_rn(o0));
            float h1 = __bfloat162float(__float2bfloat16_rn(o1));
            float h2 = __bfloat162float(__float2bfloat16_rn(o2));
            float h3 = __bfloat162float(__float2bfloat16_rn(o3));
            *(uint2*)(ah + base + 4 * w) = make_uint2(pkbf(h0, h1), pkbf(h2, h3));
            *(uint2*)(al + base + 4 * w) = make_uint2(pkbf(o0 - h0, o1 - h1), pkbf(o2 - h2, o3 - h3));
        }
    }
}

// ---------------- launch ----------------
extern "C" void kernel_launch(void* const* d_in, const int* in_sizes, int n_in,
                              void* d_out, int out_size)
{
    const float* inputs = (const float*)d_in[0];
    const float* ln1s   = (const float*)d_in[1];
    const float* ln1b   = (const float*)d_in[2];
    const float* wq     = (const float*)d_in[3];
    const float* wk     = (const float*)d_in[4];
    const float* wv     = (const float*)d_in[5];
    const float* wo     = (const float*)d_in[6];
    const float* ln2s   = (const float*)d_in[7];
    const float* ln2b   = (const float*)d_in[8];
    const float* w1     = (const float*)d_in[9];
    const float* b1     = (const float*)d_in[10];
    const float* w2     = (const float*)d_in[11];
    const float* b2     = (const float*)d_in[12];
    float* out = (float*)d_out;

    float *q, *k, *v, *x2, *ckv, *cks, *kvpre, *kspre;
    bf16 *xh, *xl, *ah, *al, *yh, *yl, *h1h, *h1l;
    bf16 *wqkvt_h, *wqkvt_l, *wot_h, *wot_l, *w1t_h, *w1t_l, *w2t_h, *w2t_l;
    cudaGetSymbolAddress((void**)&q,     g_q);
    cudaGetSymbolAddress((void**)&k,     g_k);
    cudaGetSymbolAddress((void**)&v,     g_v);
    cudaGetSymbolAddress((void**)&x2,    g_x2);
    cudaGetSymbolAddress((void**)&ckv,   g_ckv);
    cudaGetSymbolAddress((void**)&cks,   g_cks);
    cudaGetSymbolAddress((void**)&kvpre, g_kvpre);
    cudaGetSymbolAddress((void**)&kspre, g_kspre);
    cudaGetSymbolAddress((void**)&xh,  g_xh);  cudaGetSymbolAddress((void**)&xl,  g_xl);
    cudaGetSymbolAddress((void**)&ah,  g_ah);  cudaGetSymbolAddress((void**)&al,  g_al);
    cudaGetSymbolAddress((void**)&yh,  g_yh);  cudaGetSymbolAddress((void**)&yl,  g_yl);
    cudaGetSymbolAddress((void**)&h1h, g_h1h); cudaGetSymbolAddress((void**)&h1l, g_h1l);
    cudaGetSymbolAddress((void**)&wqkvt_h, g_wqkvt_h); cudaGetSymbolAddress((void**)&wqkvt_l, g_wqkvt_l);
    cudaGetSymbolAddress((void**)&wot_h, g_wot_h); cudaGetSymbolAddress((void**)&wot_l, g_wot_l);
    cudaGetSymbolAddress((void**)&w1t_h, g_w1t_h); cudaGetSymbolAddress((void**)&w1t_l, g_w1t_l);
    cudaGetSymbolAddress((void**)&w2t_h, g_w2t_h); cudaGetSymbolAddress((void**)&w2t_l, g_w2t_l);

    cudaFuncSetAttribute(attn_out_kernel,
                         cudaFuncAttributeMaxDynamicSharedMemorySize, ATTN_SMEM_BYTES);
    cudaFuncSetAttribute(mma_gemm<2>, cudaFuncAttributeMaxDynamicSharedMemorySize, GEMM_SMEM_BYTES);
    cudaFuncSetAttribute(mma_gemm<3>, cudaFuncAttributeMaxDynamicSharedMemorySize, GEMM_SMEM_BYTES);
    cudaFuncSetAttribute(mma_gemm<4>, cudaFuncAttributeMaxDynamicSharedMemorySize, GEMM_SMEM_BYTES);
    cudaFuncSetAttribute(mma_gemm<5>, cudaFuncAttributeMaxDynamicSharedMemorySize, GEMM_SMEM_BYTES);

    // 0) fused weight transpose + split (one launch for all 6 weights)
    wsplit_all<<<12288, 256>>>(wq, wk, wv, wo, w1, w2);

    // 1) LN1 -> split bf16
    ln_kernel<<<ROWS, 256>>>(inputs, ln1s, ln1b, xh, xl);

    // 2) fused QKV projection (phi fused for q,k segments; v plain)
    mma_gemm<5><<<dim3(3 * DD / 128, ROWS / 128), 128, GEMM_SMEM_BYTES>>>(
        xh, xl, wqkvt_h, wqkvt_l, q, k, v, nullptr, nullptr, nullptr, nullptr,
        ROWS, 3 * DD, DD);

    // 3) chunked causal linear attention
    attn_chunk_kernel<<<NCHUNKS_TOT, 512>>>(k, v, ckv, cks);
    attn_pre_kernel<<<NCHUNKS_TOT, 256>>>(ckv, cks, kvpre, kspre);
    attn_out_kernel<<<NCHUNKS_TOT, 256, ATTN_SMEM_BYTES>>>(q, k, v, kvpre, kspre, ah, al);

    // 4) output projection + residual -> x2
    mma_gemm<2><<<dim3(DD / 128, ROWS / 128), 128, GEMM_SMEM_BYTES>>>(
        ah, al, wot_h, wot_l, x2, nullptr, nullptr, nullptr, nullptr, nullptr, inputs,
        ROWS, DD, DD);

    // 5) LN2 -> split bf16
    ln_kernel<<<ROWS, 256>>>(x2, ln2s, ln2b, yh, yl);

    // 6) MLP
    mma_gemm<3><<<dim3(MLPD / 128, ROWS / 128), 128, GEMM_SMEM_BYTES>>>(
        yh, yl, w1t_h, w1t_l, nullptr, nullptr, nullptr, h1h, h1l, b1, nullptr,
        ROWS, MLPD, DD);
    mma_gemm<4><<<dim3(DD / 128, ROWS / 128), 128, GEMM_SMEM_BYTES>>>(
        h1h, h1l, w2t_h, w2t_l, out, nullptr, nullptr, nullptr, nullptr, b2, x2,
        ROWS, DD, MLPD);
}

// round 15
// speedup vs baseline: 1.3141x; 1.3141x over previous
#include <cuda_runtime.h>
#include <cuda_fp16.h>
#include <math.h>
#include <stdint.h>

// ---------------- problem constants ----------------
#define BB   2
#define SS   2048
#define DD   1024
#define HH   16
#define DHH  64
#define MLPD 4096
#define ROWS (BB*SS)          // 4096 tokens
#define CCH  128              // attention chunk length
#define NCH  (SS/CCH)         // 16 chunks per sequence
#define BHN  (BB*HH)          // 32 (b,h) pairs
#define NCHUNKS_TOT (BHN*NCH) // 512

typedef __half h16;

// ---------------- scratch (device globals; no allocation allowed) ----------------
__device__ float g_q   [ROWS*DD];
__device__ float g_k   [ROWS*DD];
__device__ float g_v   [ROWS*DD];
__device__ float g_x2  [ROWS*DD];
// single-fp16 activations
__device__ h16 g_xh [ROWS*DD];
__device__ h16 g_ah [ROWS*DD];
__device__ h16 g_yh [ROWS*DD];
__device__ h16 g_h1h[ROWS*MLPD];
// transposed split-fp16 weights: Bt[N][K]
__device__ h16 g_wqkvt_h[3*DD*DD], g_wqkvt_l[3*DD*DD];   // q|k|v segments
__device__ h16 g_wot_h[DD*DD],   g_wot_l[DD*DD];
__device__ h16 g_w1t_h[DD*MLPD], g_w1t_l[DD*MLPD];
__device__ h16 g_w2t_h[MLPD*DD], g_w2t_l[MLPD*DD];
// attention scratch
__device__ float g_ckv  [NCHUNKS_TOT*DHH*DHH];
__device__ float g_cks  [NCHUNKS_TOT*DHH];
__device__ float g_kvpre[NCHUNKS_TOT*DHH*DHH];
__device__ float g_kspre[NCHUNKS_TOT*DHH];

// ---------------- helpers ----------------
__device__ __forceinline__ float gelu_t(float x) {
    float x3 = x * x * x;
    float t = tanhf(0.7978845608028654f * (x + 0.044715f * x3));
    return 0.5f * x * (1.0f + t);
}
__device__ __forceinline__ unsigned pkh(float a, float b) {
    __half2 t = __floats2half2_rn(a, b);
    return *reinterpret_cast<unsigned*>(&t);
}
__device__ __forceinline__ uint32_t s2u(const void* p) {
    return (uint32_t)__cvta_generic_to_shared(p);
}
__device__ __forceinline__ void cpa16(uint32_t s, const void* g) {
    asm volatile("cp.async.cg.shared.global [%0], [%1], 16;" :: "r"(s), "l"(g));
}
#define CPA_COMMIT() asm volatile("cp.async.commit_group;" ::: "memory")
#define CPA_WAIT0()  asm volatile("cp.async.wait_group 0;" ::: "memory")

__device__ __forceinline__ void ldsm4(uint32_t& r0, uint32_t& r1, uint32_t& r2,
                                      uint32_t& r3, uint32_t a) {
    asm volatile("ldmatrix.sync.aligned.m8n8.x4.shared.b16 {%0,%1,%2,%3}, [%4];"
                 : "=r"(r0), "=r"(r1), "=r"(r2), "=r"(r3) : "r"(a));
}
__device__ __forceinline__ void ldsm2(uint32_t& r0, uint32_t& r1, uint32_t a) {
    asm volatile("ldmatrix.sync.aligned.m8n8.x2.shared.b16 {%0,%1}, [%2];"
                 : "=r"(r0), "=r"(r1) : "r"(a));
}
__device__ __forceinline__ void hmma(float* c, const uint32_t* a, const uint32_t* b) {
    asm volatile(
        "mma.sync.aligned.m16n8k16.row.col.f32.f16.f16.f32 "
        "{%0,%1,%2,%3}, {%4,%5,%6,%7}, {%8,%9}, {%0,%1,%2,%3};"
        : "+f"(c[0]), "+f"(c[1]), "+f"(c[2]), "+f"(c[3])
        : "r"(a[0]), "r"(a[1]), "r"(a[2]), "r"(a[3]), "r"(b[0]), "r"(b[1]));
}

// ---------------- fused weight transpose + fp16 split (single launch) ----------------
__global__ void __launch_bounds__(256)
wsplit_all(const float* __restrict__ wq, const float* __restrict__ wk,
           const float* __restrict__ wv, const float* __restrict__ wo,
           const float* __restrict__ w1, const float* __restrict__ w2)
{
    int id = blockIdx.x;
    const float* W;
    h16 *Th, *Tl;
    int K, N, n0, k0;
    if (id < 3072) {
        int w = id >> 10, tile = id & 1023;
        W = (w == 0) ? wq : (w == 1) ? wk : wv;
        K = DD; N = DD;
        Th = g_wqkvt_h + (size_t)w * DD * DD;
        Tl = g_wqkvt_l + (size_t)w * DD * DD;
        n0 = (tile & 31) * 32; k0 = (tile >> 5) * 32;
    } else if (id < 4096) {
        int tile = id - 3072;
        W = wo; K = DD; N = DD;
        Th = g_wot_h; Tl = g_wot_l;
        n0 = (tile & 31) * 32; k0 = (tile >> 5) * 32;
    } else if (id < 8192) {
        int tile = id - 4096;
        W = w1; K = DD; N = MLPD;
        Th = g_w1t_h; Tl = g_w1t_l;
        n0 = (tile & 127) * 32; k0 = (tile >> 7) * 32;
    } else {
        int tile = id - 8192;
        W = w2; K = MLPD; N = DD;
        Th = g_w2t_h; Tl = g_w2t_l;
        n0 = (tile & 31) * 32; k0 = (tile >> 5) * 32;
    }

    __shared__ float t[32][33];
    int tx = threadIdx.x & 31, ty = threadIdx.x >> 5;
#pragma unroll
    for (int r = 0; r < 4; r++) {
        int k = k0 + ty + r * 8;
        t[ty + r * 8][tx] = W[(size_t)k * N + n0 + tx];
    }
    __syncthreads();
#pragma unroll
    for (int r = 0; r < 4; r++) {
        int n = n0 + ty + r * 8;
        float vv = t[tx][ty + r * 8];
        h16 h = __float2half_rn(vv);
        Th[(size_t)n * K + k0 + tx] = h;
        Tl[(size_t)n * K + k0 + tx] = __float2half_rn(vv - __half2float(h));
    }
}

// ---------------- LayerNorm -> single fp16 ----------------
__global__ void __launch_bounds__(256)
ln_kernel(const float* __restrict__ x, const float* __restrict__ sc,
          const float* __restrict__ bi, h16* __restrict__ yh)
{
    int row = blockIdx.x;
    int t = threadIdx.x;
    const float4* xr = (const float4*)(x + (size_t)row * DD);
    float4 v = xr[t];
    float s  = v.x + v.y + v.z + v.w;
    float ss = v.x*v.x + v.y*v.y + v.z*v.z + v.w*v.w;
#pragma unroll
    for (int o = 16; o > 0; o >>= 1) {
        s  += __shfl_xor_sync(0xffffffffu, s,  o);
        ss += __shfl_xor_sync(0xffffffffu, ss, o);
    }
    __shared__ float sh[16];
    int w = t >> 5, l = t & 31;
    if (l == 0) { sh[w] = s; sh[8 + w] = ss; }
    __syncthreads();
    if (t < 32) {
        s  = (t < 8) ? sh[t]     : 0.f;
        ss = (t < 8) ? sh[8 + t] : 0.f;
#pragma unroll
        for (int o = 4; o > 0; o >>= 1) {
            s  += __shfl_xor_sync(0xffffffffu, s,  o);
            ss += __shfl_xor_sync(0xffffffffu, ss, o);
        }
        if (t == 0) { sh[0] = s; sh[8] = ss; }
    }
    __syncthreads();
    float mean = sh[0] * (1.0f / (float)DD);
    float var  = sh[8] * (1.0f / (float)DD) - mean * mean;
    float rs = rsqrtf(var + 1e-6f);
    float4 scv = ((const float4*)sc)[t];
    float4 biv = ((const float4*)bi)[t];
    float o0 = (v.x - mean) * rs * scv.x + biv.x;
    float o1 = (v.y - mean) * rs * scv.y + biv.y;
    float o2 = (v.z - mean) * rs * scv.z + biv.z;
    float o3 = (v.w - mean) * rs * scv.w + biv.w;
    *(uint2*)(yh + (size_t)row * DD + t * 4) =
        make_uint2(pkh(o0, o1), pkh(o2, o3));
}

// ---------------- mma.sync 2-product fp16 GEMM ----------------
// A: single fp16. B: split fp16 (Bh + Bl). D = A*Bh + A*Bl (exact in B).
// CTA 128x128, 256 threads (8 warps, 2x4), warp tile 64x32, BK=32, 2-stage.
// EPI: 2 +res fp32 ; 3 +bias gelu -> fp16 ; 4 +bias +res fp32 ;
//      5 fused QKV (seg = gcol>>10: 0,1 relu+eps ; 2 plain) fp32
#define BKK        32
#define ROWSTRIDE  40                      // fp16 elems per smem row (80B)
#define MAT_B      (128*ROWSTRIDE*2)       // 10240 bytes per matrix per stage
#define STAGE_B    (3*MAT_B)               // 30720 bytes per stage (A, Bh, Bl)
#define GEMM_SMEM_BYTES (128*132*4)        // 67584 (epilogue stage dominates 2*STAGE_B)

template <int EPI>
__global__ void __launch_bounds__(256, 2)
mma_gemm(const h16* __restrict__ A,
         const h16* __restrict__ Bh, const h16* __restrict__ Bl,
         float* __restrict__ C, float* __restrict__ C2, float* __restrict__ C3,
         h16* __restrict__ Ch,
         const float* __restrict__ bias, const float* __restrict__ res,
         int M, int N, int K)
{
    extern __shared__ h16 smbuf[];
    uint32_t sb = s2u(smbuf);
    int tid = threadIdx.x, lane = tid & 31, wid = tid >> 5;
    int wm = wid >> 2, wn = wid & 3;              // 2 x 4 warp grid, 64x32 tiles
    int m0 = blockIdx.y * 128, n0 = blockIdx.x * 128;

    float acc[4][4][4];
#pragma unroll
    for (int f = 0; f < 4; f++)
#pragma unroll
        for (int g = 0; g < 4; g++)
#pragma unroll
            for (int e = 0; e < 4; e++) acc[f][g][e] = 0.f;

    auto load_stage = [&](int kt, int st) {
        int koff = kt * BKK;
        uint32_t s0 = sb + (uint32_t)st * STAGE_B;
#pragma unroll
        for (int r = 0; r < 2; r++) {
            int e = tid + 256 * r;                // 0..511
            int row = e >> 2, q = e & 3;
            uint32_t so = (uint32_t)(row * ROWSTRIDE + q * 8) * 2;
            size_t ga = (size_t)(m0 + row) * K + koff + q * 8;
            size_t gb = (size_t)(n0 + row) * K + koff + q * 8;
            cpa16(s0 + 0 * MAT_B + so, A  + ga);
            cpa16(s0 + 1 * MAT_B + so, Bh + gb);
            cpa16(s0 + 2 * MAT_B + so, Bl + gb);
        }
    };

    load_stage(0, 0);
    CPA_COMMIT();
    CPA_WAIT0();
    __syncthreads();

    const int KT = K / BKK;
    for (int kt = 0; kt < KT; ++kt) {
        int st = kt & 1;
        if (kt + 1 < KT) { load_stage(kt + 1, st ^ 1); CPA_COMMIT(); }

        uint32_t sA = sb + (uint32_t)st * STAGE_B;
        uint32_t sB = sA + MAT_B;
#pragma unroll
        for (int ks = 0; ks < 2; ++ks) {
            int kb = ks * 16;
            uint32_t ar[4][4], bh[4][2], bl[4][2];
#pragma unroll
            for (int f = 0; f < 4; f++) {
                int row = wm * 64 + f * 16 + (lane & 7) + ((lane >> 3) & 1) * 8;
                int col = kb + ((lane >> 4) << 3);
                uint32_t ad = sA + (uint32_t)(row * ROWSTRIDE + col) * 2;
                ldsm4(ar[f][0], ar[f][1], ar[f][2], ar[f][3], ad);
            }
#pragma unroll
            for (int g = 0; g < 4; g++) {
                int l2 = lane & 15;
                int nrow = wn * 32 + g * 8 + (l2 & 7);
                int col = kb + ((l2 >> 3) << 3);
                uint32_t bd = sB + (uint32_t)(nrow * ROWSTRIDE + col) * 2;
                ldsm2(bh[g][0], bh[g][1], bd);
                ldsm2(bl[g][0], bl[g][1], bd + MAT_B);
            }
#pragma unroll
            for (int f = 0; f < 4; f++)
#pragma unroll
                for (int g = 0; g < 4; g++) hmma(acc[f][g], ar[f], bh[g]);
#pragma unroll
            for (int f = 0; f < 4; f++)
#pragma unroll
                for (int g = 0; g < 4; g++) hmma(acc[f][g], ar[f], bl[g]);
        }
        if (kt + 1 < KT) CPA_WAIT0();
        __syncthreads();
    }

    // ---- epilogue: regs -> smem float stage -> coalesced global stores ----
    float* stg = (float*)smbuf;                   // 128 x 132 floats
#pragma unroll
    for (int f = 0; f < 4; f++) {
        int mrow = wm * 64 + f * 16 + (lane >> 2);
#pragma unroll
        for (int g = 0; g < 4; g++) {
            int ncol = wn * 32 + g * 8 + (lane & 3) * 2;
            stg[(mrow    ) * 132 + ncol    ] = acc[f][g][0];
            stg[(mrow    ) * 132 + ncol + 1] = acc[f][g][1];
            stg[(mrow + 8) * 132 + ncol    ] = acc[f][g][2];
            stg[(mrow + 8) * 132 + ncol + 1] = acc[f][g][3];
        }
    }
    __syncthreads();

#pragma unroll
    for (int r = 0; r < 16; r++) {
        int e = tid + 256 * r;
        int row = e >> 5, q = e & 31;
        float4 o = *(float4*)&stg[row * 132 + q * 4];
        int grow = m0 + row, gcol = n0 + q * 4;
        size_t gi = (size_t)grow * N + gcol;

        if (EPI == 2) {
            float4 rr = *(const float4*)(res + gi);
            o.x += rr.x; o.y += rr.y; o.z += rr.z; o.w += rr.w;
            *(float4*)(C + gi) = o;
        } else if (EPI == 3) {
            float4 bb = *(const float4*)(bias + gcol);
            o.x = gelu_t(o.x + bb.x); o.y = gelu_t(o.y + bb.y);
            o.z = gelu_t(o.z + bb.z); o.w = gelu_t(o.w + bb.w);
            *(uint2*)(Ch + gi) = make_uint2(pkh(o.x, o.y), pkh(o.z, o.w));
        } else if (EPI == 4) {
            float4 bb = *(const float4*)(bias + gcol);
            float4 rr = *(const float4*)(res + gi);
            o.x += bb.x + rr.x; o.y += bb.y + rr.y;
            o.z += bb.z + rr.z; o.w += bb.w + rr.w;
            *(float4*)(C + gi) = o;
        } else {  // EPI == 5: fused QKV
            int seg = gcol >> 10;
            int cin = gcol & 1023;
            float* dst = (seg == 0) ? C : (seg == 1) ? C2 : C3;
            if (seg < 2) {
                o.x = fmaxf(o.x, 0.f) + 1e-3f;
                o.y = fmaxf(o.y, 0.f) + 1e-3f;
                o.z = fmaxf(o.z, 0.f) + 1e-3f;
                o.w = fmaxf(o.w, 0.f) + 1e-3f;
            }
            *(float4*)(dst + (size_t)grow * DD + cin) = o;
        }
    }
}

// ---------------- attention pass A: per-chunk KV = phiK^T V and ksum ----------------
__global__ void __launch_bounds__(256)
attn_chunk_kernel(const float* __restrict__ Kk, const float* __restrict__ V,
                  float* __restrict__ ckv, float* __restrict__ cks)
{
    __shared__ float sK[64][64];
    __shared__ float sV[64][64];
    int g = blockIdx.x;
    int c = g & 15, bh = g >> 4;
    int h = bh & 15, b = bh >> 4;
    int row0 = b * SS + c * CCH;
    int colBase = h * 64;
    int t = threadIdx.x;
    int m = t >> 2;
    int d0 = (t & 3) * 16;

    float acc[16];
#pragma unroll
    for (int w = 0; w < 16; w++) acc[w] = 0.f;
    float ks = 0.f;

    for (int half = 0; half < 2; ++half) {
#pragma unroll
        for (int r = 0; r < 16; r++) {
            int e = t + 256 * r;
            int s = e >> 6, d = e & 63;
            size_t gi = (size_t)(row0 + half * 64 + s) * DD + colBase + d;
            sK[s][d] = Kk[gi];
            sV[s][d] = V[gi];
        }
        __syncthreads();
        for (int s = 0; s < 64; s++) {
            float kk = sK[s][m];
            if ((t & 3) == 0) ks += kk;
            const float* vr = &sV[s][d0];
#pragma unroll
            for (int w = 0; w < 4; w++) {
                float4 vv = *(const float4*)(vr + 4 * w);
                acc[4 * w + 0] += kk * vv.x;
                acc[4 * w + 1] += kk * vv.y;
                acc[4 * w + 2] += kk * vv.z;
                acc[4 * w + 3] += kk * vv.w;
            }
        }
        __syncthreads();
    }
    float* op = ckv + (size_t)g * (DHH * DHH) + m * 64 + d0;
#pragma unroll
    for (int w = 0; w < 4; w++)
        *(float4*)(op + 4 * w) = make_float4(acc[4*w], acc[4*w+1], acc[4*w+2], acc[4*w+3]);
    if ((t & 3) == 0) cks[g * 64 + m] = ks;
}

// ---------------- attention pass B: parallel exclusive prefix (gather form) ----------------
__global__ void __launch_bounds__(256)
attn_pre_kernel(const float* __restrict__ ckv, const float* __restrict__ cks,
                float* __restrict__ kvpre, float* __restrict__ kspre)
{
    int g = blockIdx.x;
    int c = g & 15, bh = g >> 4;
    int t = threadIdx.x;
    float run[16];
#pragma unroll
    for (int r = 0; r < 16; r++) run[r] = 0.f;
    for (int cc = 0; cc < c; cc++) {
        const float* p = ckv + ((size_t)(bh * NCH + cc)) * (DHH * DHH);
#pragma unroll
        for (int r = 0; r < 16; r++) run[r] += p[t + 256 * r];
    }
    float* o = kvpre + (size_t)g * (DHH * DHH);
#pragma unroll
    for (int r = 0; r < 16; r++) o[t + 256 * r] = run[r];
    if (t < 64) {
        float kr = 0.f;
        for (int cc = 0; cc < c; cc++) kr += cks[(bh * NCH + cc) * 64 + t];
        kspre[g * 64 + t] = kr;
    }
}

// ---------------- attention pass C: per-chunk causal output -> single fp16 ----------------
#define ATTN_SMEM_FLOATS (64*132 + 64*132 + 128*68 + 64*68 + 64 + 128*132)
#define ATTN_SMEM_BYTES  (ATTN_SMEM_FLOATS * 4)

__global__ void __launch_bounds__(256)
attn_out_kernel(const float* __restrict__ Q, const float* __restrict__ Kk,
                const float* __restrict__ V, const float* __restrict__ kvpre,
                const float* __restrict__ kspre, h16* __restrict__ ah)
{
    extern __shared__ float sm[];
    float* sQt = sm;
    float* sKt = sQt + 64 * 132;
    float* sV  = sKt + 64 * 132;
    float* sKV = sV  + 128 * 68;
    float* sKs = sKV + 64 * 68;
    float* sA  = sKs + 64;

    int g = blockIdx.x;
    int c = g & 15, bh = g >> 4;
    int h = bh & 15, b = bh >> 4;
    int row0 = b * SS + c * CCH;
    int colBase = h * 64;
    int t = threadIdx.x;

#pragma unroll
    for (int r = 0; r < 32; r++) {
        int e = t + 256 * r;
        int s = e >> 6, m = e & 63;
        size_t gi = (size_t)(row0 + s) * DD + colBase + m;
        sQt[m * 132 + s] = Q[gi];
        sKt[m * 132 + s] = Kk[gi];
        sV[s * 68 + m]   = V[gi];
    }
#pragma unroll
    for (int r = 0; r < 16; r++) {
        int e = t + 256 * r;
        sKV[(e >> 6) * 68 + (e & 63)] = kvpre[(size_t)g * (DHH * DHH) + e];
    }
    if (t < 64) sKs[t] = kspre[g * 64 + t];
    __syncthreads();

    {
        int ty = t >> 4, tx = t & 15;
        float accA[8][8];
#pragma unroll
        for (int i = 0; i < 8; i++)
#pragma unroll
            for (int j = 0; j < 8; j++) accA[i][j] = 0.f;
        for (int kk = 0; kk < 64; kk++) {
            const float* qr = &sQt[kk * 132 + ty * 8];
            float4 q0 = *(const float4*)qr;
            float4 q1 = *(const float4*)(qr + 4);
            const float* kr = &sKt[kk * 132 + tx * 8];
            float4 k0 = *(const float4*)kr;
            float4 k1 = *(const float4*)(kr + 4);
            float qa[8] = { q0.x, q0.y, q0.z, q0.w, q1.x, q1.y, q1.z, q1.w };
            float kb[8] = { k0.x, k0.y, k0.z, k0.w, k1.x, k1.y, k1.z, k1.w };
#pragma unroll
            for (int i = 0; i < 8; i++)
#pragma unroll
                for (int j = 0; j < 8; j++) accA[i][j] += qa[i] * kb[j];
        }
        int i0 = ty * 8, j0 = tx * 8;
#pragma unroll
        for (int i = 0; i < 8; i++)
#pragma unroll
            for (int j = 0; j < 8; j++)
                sA[(i0 + i) * 132 + (j0 + j)] = (j0 + j <= i0 + i) ? accA[i][j] : 0.f;
    }
    __syncthreads();

    {
        int i = t >> 1;
        int d0 = (t & 1) * 32;
        float acc[32];
#pragma unroll
        for (int w = 0; w < 32; w++) acc[w] = 0.f;
        float den = 0.f;
        for (int j = 0; j < 128; j++) {
            float a = sA[i * 132 + j];
            den += a;
            const float* vr = &sV[j * 68 + d0];
#pragma unroll
            for (int w = 0; w < 8; w++) {
                float4 vv = *(const float4*)(vr + 4 * w);
                acc[4 * w + 0] += a * vv.x;
                acc[4 * w + 1] += a * vv.y;
                acc[4 * w + 2] += a * vv.z;
                acc[4 * w + 3] += a * vv.w;
            }
        }
        for (int m = 0; m < 64; m++) {
            float p = sQt[m * 132 + i];
            den += p * sKs[m];
            const float* kr = &sKV[m * 68 + d0];
#pragma unroll
            for (int w = 0; w < 8; w++) {
                float4 vv = *(const float4*)(kr + 4 * w);
                acc[4 * w + 0] += p * vv.x;
                acc[4 * w + 1] += p * vv.y;
                acc[4 * w + 2] += p * vv.z;
                acc[4 * w + 3] += p * vv.w;
            }
        }
        float inv = 1.0f / den;
        size_t base = (size_t)(row0 + i) * DD + colBase + d0;
#pragma unroll
        for (int w = 0; w < 8; w++) {
            float o0 = acc[4*w+0] * inv, o1 = acc[4*w+1] * inv;
            float o2 = acc[4*w+2] * inv, o3 = acc[4*w+3] * inv;
            *(uint2*)(ah + base + 4 * w) = make_uint2(pkh(o0, o1), pkh(o2, o3));
        }
    }
}

// ---------------- launch ----------------
extern "C" void kernel_launch(void* const* d_in, const int* in_sizes, int n_in,
                              void* d_out, int out_size)
{
    const float* inputs = (const float*)d_in[0];
    const float* ln1s   = (const float*)d_in[1];
    const float* ln1b   = (const float*)d_in[2];
    const float* wq     = (const float*)d_in[3];
    const float* wk     = (const float*)d_in[4];
    const float* wv     = (const float*)d_in[5];
    const float* wo     = (const float*)d_in[6];
    const float* ln2s   = (const float*)d_in[7];
    const float* ln2b   = (const float*)d_in[8];
    const float* w1     = (const float*)d_in[9];
    const float* b1     = (const float*)d_in[10];
    const float* w2     = (const float*)d_in[11];
    const float* b2     = (const float*)d_in[12];
    float* out = (float*)d_out;

    float *q, *k, *v, *x2, *ckv, *cks, *kvpre, *kspre;
    h16 *xh, *ah, *yh, *h1h;
    h16 *wqkvt_h, *wqkvt_l, *wot_h, *wot_l, *w1t_h, *w1t_l, *w2t_h, *w2t_l;
    cudaGetSymbolAddress((void**)&q,     g_q);
    cudaGetSymbolAddress((void**)&k,     g_k);
    cudaGetSymbolAddress((void**)&v,     g_v);
    cudaGetSymbolAddress((void**)&x2,    g_x2);
    cudaGetSymbolAddress((void**)&ckv,   g_ckv);
    cudaGetSymbolAddress((void**)&cks,   g_cks);
    cudaGetSymbolAddress((void**)&kvpre, g_kvpre);
    cudaGetSymbolAddress((void**)&kspre, g_kspre);
    cudaGetSymbolAddress((void**)&xh,  g_xh);
    cudaGetSymbolAddress((void**)&ah,  g_ah);
    cudaGetSymbolAddress((void**)&yh,  g_yh);
    cudaGetSymbolAddress((void**)&h1h, g_h1h);
    cudaGetSymbolAddress((void**)&wqkvt_h, g_wqkvt_h); cudaGetSymbolAddress((void**)&wqkvt_l, g_wqkvt_l);
    cudaGetSymbolAddress((void**)&wot_h, g_wot_h); cudaGetSymbolAddress((void**)&wot_l, g_wot_l);
    cudaGetSymbolAddress((void**)&w1t_h, g_w1t_h); cudaGetSymbolAddress((void**)&w1t_l, g_w1t_l);
    cudaGetSymbolAddress((void**)&w2t_h, g_w2t_h); cudaGetSymbolAddress((void**)&w2t_l, g_w2t_l);

    cudaFuncSetAttribute(attn_out_kernel,
                         cudaFuncAttributeMaxDynamicSharedMemorySize, ATTN_SMEM_BYTES);
    cudaFuncSetAttribute(mma_gemm<2>, cudaFuncAttributeMaxDynamicSharedMemorySize, GEMM_SMEM_BYTES);
    cudaFuncSetAttribute(mma_gemm<3>, cudaFuncAttributeMaxDynamicSharedMemorySize, GEMM_SMEM_BYTES);
    cudaFuncSetAttribute(mma_gemm<4>, cudaFuncAttributeMaxDynamicSharedMemorySize, GEMM_SMEM_BYTES);
    cudaFuncSetAttribute(mma_gemm<5>, cudaFuncAttributeMaxDynamicSharedMemorySize, GEMM_SMEM_BYTES);

    // 0) fused weight transpose + fp16 split (one launch for all 6 weights)
    wsplit_all<<<12288, 256>>>(wq, wk, wv, wo, w1, w2);

    // 1) LN1 -> fp16
    ln_kernel<<<ROWS, 256>>>(inputs, ln1s, ln1b, xh);

    // 2) fused QKV projection (phi fused for q,k segments; v plain)
    mma_gemm<5><<<dim3(3 * DD / 128, ROWS / 128), 256, GEMM_SMEM_BYTES>>>(
        xh, wqkvt_h, wqkvt_l, q, k, v, nullptr, nullptr, nullptr,
        ROWS, 3 * DD, DD);

    // 3) chunked causal linear attention
    attn_chunk_kernel<<<NCHUNKS_TOT, 256>>>(k, v, ckv, cks);
    attn_pre_kernel<<<NCHUNKS_TOT, 256>>>(ckv, cks, kvpre, kspre);
    attn_out_kernel<<<NCHUNKS_TOT, 256, ATTN_SMEM_BYTES>>>(q, k, v, kvpre, kspre, ah);

    // 4) output projection + residual -> x2
    mma_gemm<2><<<dim3(DD / 128, ROWS / 128), 256, GEMM_SMEM_BYTES>>>(
        ah, wot_h, wot_l, x2, nullptr, nullptr, nullptr, nullptr, inputs,
        ROWS, DD, DD);

    // 5) LN2 -> fp16
    ln_kernel<<<ROWS, 256>>>(x2, ln2s, ln2b, yh);

    // 6) MLP
    mma_gemm<3><<<dim3(MLPD / 128, ROWS / 128), 256, GEMM_SMEM_BYTES>>>(
        yh, w1t_h, w1t_l, nullptr, nullptr, nullptr, h1h, b1, nullptr,
        ROWS, MLPD, DD);
    mma_gemm<4><<<dim3(DD / 128, ROWS / 128), 256, GEMM_SMEM_BYTES>>>(
        h1h, w2t_h, w2t_l, out, nullptr, nullptr, nullptr, b2, x2,
        ROWS, DD, MLPD);
}

// round 16
// speedup vs baseline: 1.8829x; 1.4328x over previous
#include <cuda_runtime.h>
#include <cuda_fp16.h>
#include <math.h>
#include <stdint.h>

// ---------------- problem constants ----------------
#define BB   2
#define SS   2048
#define DD   1024
#define HH   16
#define DHH  64
#define MLPD 4096
#define ROWS (BB*SS)          // 4096 tokens
#define CCH  128              // attention chunk length
#define NCH  (SS/CCH)         // 16 chunks per sequence
#define BHN  (BB*HH)          // 32 (b,h) pairs
#define NCHUNKS_TOT (BHN*NCH) // 512

typedef __half h16;

// ---------------- scratch (device globals; no allocation allowed) ----------------
__device__ float g_q   [ROWS*DD];
__device__ float g_k   [ROWS*DD];
__device__ float g_v   [ROWS*DD];
__device__ float g_x2  [ROWS*DD];
// single-fp16 activations
__device__ h16 g_xh [ROWS*DD];
__device__ h16 g_ah [ROWS*DD];
__device__ h16 g_yh [ROWS*DD];
__device__ h16 g_h1h[ROWS*MLPD];
// transposed single-fp16 weights: Bt[N][K]
__device__ h16 g_wqkvt[3*DD*DD];   // q|k|v segments
__device__ h16 g_wot[DD*DD];
__device__ h16 g_w1t[DD*MLPD];
__device__ h16 g_w2t[MLPD*DD];
// attention scratch
__device__ float g_ckv  [NCHUNKS_TOT*DHH*DHH];
__device__ float g_cks  [NCHUNKS_TOT*DHH];
__device__ float g_kvpre[NCHUNKS_TOT*DHH*DHH];
__device__ float g_kspre[NCHUNKS_TOT*DHH];

// ---------------- helpers ----------------
__device__ __forceinline__ float gelu_t(float x) {
    float x3 = x * x * x;
    float t = tanhf(0.7978845608028654f * (x + 0.044715f * x3));
    return 0.5f * x * (1.0f + t);
}
__device__ __forceinline__ unsigned pkh(float a, float b) {
    __half2 t = __floats2half2_rn(a, b);
    return *reinterpret_cast<unsigned*>(&t);
}
__device__ __forceinline__ uint32_t s2u(const void* p) {
    return (uint32_t)__cvta_generic_to_shared(p);
}
__device__ __forceinline__ void cpa16(uint32_t s, const void* g) {
    asm volatile("cp.async.cg.shared.global [%0], [%1], 16;" :: "r"(s), "l"(g));
}
#define CPA_COMMIT() asm volatile("cp.async.commit_group;" ::: "memory")
#define CPA_WAIT0()  asm volatile("cp.async.wait_group 0;" ::: "memory")

__device__ __forceinline__ void ldsm4(uint32_t& r0, uint32_t& r1, uint32_t& r2,
                                      uint32_t& r3, uint32_t a) {
    asm volatile("ldmatrix.sync.aligned.m8n8.x4.shared.b16 {%0,%1,%2,%3}, [%4];"
                 : "=r"(r0), "=r"(r1), "=r"(r2), "=r"(r3) : "r"(a));
}
__device__ __forceinline__ void ldsm2(uint32_t& r0, uint32_t& r1, uint32_t a) {
    asm volatile("ldmatrix.sync.aligned.m8n8.x2.shared.b16 {%0,%1}, [%2];"
                 : "=r"(r0), "=r"(r1) : "r"(a));
}
__device__ __forceinline__ void hmma(float* c, const uint32_t* a, const uint32_t* b) {
    asm volatile(
        "mma.sync.aligned.m16n8k16.row.col.f32.f16.f16.f32 "
        "{%0,%1,%2,%3}, {%4,%5,%6,%7}, {%8,%9}, {%0,%1,%2,%3};"
        : "+f"(c[0]), "+f"(c[1]), "+f"(c[2]), "+f"(c[3])
        : "r"(a[0]), "r"(a[1]), "r"(a[2]), "r"(a[3]), "r"(b[0]), "r"(b[1]));
}

// ---------------- fused weight transpose + fp16 convert (single launch) ----------------
__global__ void __launch_bounds__(256)
wsplit_all(const float* __restrict__ wq, const float* __restrict__ wk,
           const float* __restrict__ wv, const float* __restrict__ wo,
           const float* __restrict__ w1, const float* __restrict__ w2)
{
    int id = blockIdx.x;
    const float* W;
    h16 *Th;
    int K, N, n0, k0;
    if (id < 3072) {
        int w = id >> 10, tile = id & 1023;
        W = (w == 0) ? wq : (w == 1) ? wk : wv;
        K = DD; N = DD;
        Th = g_wqkvt + (size_t)w * DD * DD;
        n0 = (tile & 31) * 32; k0 = (tile >> 5) * 32;
    } else if (id < 4096) {
        int tile = id - 3072;
        W = wo; K = DD; N = DD;
        Th = g_wot;
        n0 = (tile & 31) * 32; k0 = (tile >> 5) * 32;
    } else if (id < 8192) {
        int tile = id - 4096;
        W = w1; K = DD; N = MLPD;
        Th = g_w1t;
        n0 = (tile & 127) * 32; k0 = (tile >> 7) * 32;
    } else {
        int tile = id - 8192;
        W = w2; K = MLPD; N = DD;
        Th = g_w2t;
        n0 = (tile & 31) * 32; k0 = (tile >> 5) * 32;
    }

    __shared__ float t[32][33];
    int tx = threadIdx.x & 31, ty = threadIdx.x >> 5;
#pragma unroll
    for (int r = 0; r < 4; r++) {
        int k = k0 + ty + r * 8;
        t[ty + r * 8][tx] = W[(size_t)k * N + n0 + tx];
    }
    __syncthreads();
#pragma unroll
    for (int r = 0; r < 4; r++) {
        int n = n0 + ty + r * 8;
        Th[(size_t)n * K + k0 + tx] = __float2half_rn(t[tx][ty + r * 8]);
    }
}

// ---------------- LayerNorm -> single fp16 ----------------
__global__ void __launch_bounds__(256)
ln_kernel(const float* __restrict__ x, const float* __restrict__ sc,
          const float* __restrict__ bi, h16* __restrict__ yh)
{
    int row = blockIdx.x;
    int t = threadIdx.x;
    const float4* xr = (const float4*)(x + (size_t)row * DD);
    float4 v = xr[t];
    float s  = v.x + v.y + v.z + v.w;
    float ss = v.x*v.x + v.y*v.y + v.z*v.z + v.w*v.w;
#pragma unroll
    for (int o = 16; o > 0; o >>= 1) {
        s  += __shfl_xor_sync(0xffffffffu, s,  o);
        ss += __shfl_xor_sync(0xffffffffu, ss, o);
    }
    __shared__ float sh[16];
    int w = t >> 5, l = t & 31;
    if (l == 0) { sh[w] = s; sh[8 + w] = ss; }
    __syncthreads();
    if (t < 32) {
        s  = (t < 8) ? sh[t]     : 0.f;
        ss = (t < 8) ? sh[8 + t] : 0.f;
#pragma unroll
        for (int o = 4; o > 0; o >>= 1) {
            s  += __shfl_xor_sync(0xffffffffu, s,  o);
            ss += __shfl_xor_sync(0xffffffffu, ss, o);
        }
        if (t == 0) { sh[0] = s; sh[8] = ss; }
    }
    __syncthreads();
    float mean = sh[0] * (1.0f / (float)DD);
    float var  = sh[8] * (1.0f / (float)DD) - mean * mean;
    float rs = rsqrtf(var + 1e-6f);
    float4 scv = ((const float4*)sc)[t];
    float4 biv = ((const float4*)bi)[t];
    float o0 = (v.x - mean) * rs * scv.x + biv.x;
    float o1 = (v.y - mean) * rs * scv.y + biv.y;
    float o2 = (v.z - mean) * rs * scv.z + biv.z;
    float o3 = (v.w - mean) * rs * scv.w + biv.w;
    *(uint2*)(yh + (size_t)row * DD + t * 4) =
        make_uint2(pkh(o0, o1), pkh(o2, o3));
}

// ---------------- mma.sync plain fp16 GEMM ----------------
// A, B single fp16; fp32 accumulate. CTA 128x128, 256 threads (8 warps, 2x4),
// warp tile 64x32, BK=32, 2-stage cp.async.
// EPI: 2 +res fp32 ; 3 +bias gelu -> fp16 ; 4 +bias +res fp32 ;
//      5 fused QKV (seg = gcol>>10: 0,1 relu+eps ; 2 plain) fp32
#define BKK        32
#define ROWSTRIDE  40                      // fp16 elems per smem row (80B)
#define MAT_B      (128*ROWSTRIDE*2)       // 10240 bytes per matrix per stage
#define STAGE_B    (2*MAT_B)               // 20480 bytes per stage (A, B)
#define GEMM_SMEM_BYTES (128*132*4)        // 67584 (epilogue stage dominates 2*STAGE_B=40960)

template <int EPI>
__global__ void __launch_bounds__(256, 2)
mma_gemm(const h16* __restrict__ A, const h16* __restrict__ B,
         float* __restrict__ C, float* __restrict__ C2, float* __restrict__ C3,
         h16* __restrict__ Ch,
         const float* __restrict__ bias, const float* __restrict__ res,
         int M, int N, int K)
{
    extern __shared__ h16 smbuf[];
    uint32_t sb = s2u(smbuf);
    int tid = threadIdx.x, lane = tid & 31, wid = tid >> 5;
    int wm = wid >> 2, wn = wid & 3;              // 2 x 4 warp grid, 64x32 tiles
    int m0 = blockIdx.y * 128, n0 = blockIdx.x * 128;

    float acc[4][4][4];
#pragma unroll
    for (int f = 0; f < 4; f++)
#pragma unroll
        for (int g = 0; g < 4; g++)
#pragma unroll
            for (int e = 0; e < 4; e++) acc[f][g][e] = 0.f;

    auto load_stage = [&](int kt, int st) {
        int koff = kt * BKK;
        uint32_t s0 = sb + (uint32_t)st * STAGE_B;
#pragma unroll
        for (int r = 0; r < 2; r++) {
            int e = tid + 256 * r;                // 0..511
            int row = e >> 2, q = e & 3;
            uint32_t so = (uint32_t)(row * ROWSTRIDE + q * 8) * 2;
            size_t ga = (size_t)(m0 + row) * K + koff + q * 8;
            size_t gb = (size_t)(n0 + row) * K + koff + q * 8;
            cpa16(s0 +         so, A + ga);
            cpa16(s0 + MAT_B + so, B + gb);
        }
    };

    load_stage(0, 0);
    CPA_COMMIT();
    CPA_WAIT0();
    __syncthreads();

    const int KT = K / BKK;
    for (int kt = 0; kt < KT; ++kt) {
        int st = kt & 1;
        if (kt + 1 < KT) { load_stage(kt + 1, st ^ 1); CPA_COMMIT(); }

        uint32_t sA = sb + (uint32_t)st * STAGE_B;
        uint32_t sB = sA + MAT_B;
#pragma unroll
        for (int ks = 0; ks < 2; ++ks) {
            int kb = ks * 16;
            uint32_t ar[4][4], br[4][2];
#pragma unroll
            for (int f = 0; f < 4; f++) {
                int row = wm * 64 + f * 16 + (lane & 7) + ((lane >> 3) & 1) * 8;
                int col = kb + ((lane >> 4) << 3);
                uint32_t ad = sA + (uint32_t)(row * ROWSTRIDE + col) * 2;
                ldsm4(ar[f][0], ar[f][1], ar[f][2], ar[f][3], ad);
            }
#pragma unroll
            for (int g = 0; g < 4; g++) {
                int l2 = lane & 15;
                int nrow = wn * 32 + g * 8 + (l2 & 7);
                int col = kb + ((l2 >> 3) << 3);
                uint32_t bd = sB + (uint32_t)(nrow * ROWSTRIDE + col) * 2;
                ldsm2(br[g][0], br[g][1], bd);
            }
#pragma unroll
            for (int f = 0; f < 4; f++)
#pragma unroll
                for (int g = 0; g < 4; g++) hmma(acc[f][g], ar[f], br[g]);
        }
        if (kt + 1 < KT) CPA_WAIT0();
        __syncthreads();
    }

    // ---- epilogue: regs -> smem float stage -> coalesced global stores ----
    float* stg = (float*)smbuf;                   // 128 x 132 floats
#pragma unroll
    for (int f = 0; f < 4; f++) {
        int mrow = wm * 64 + f * 16 + (lane >> 2);
#pragma unroll
        for (int g = 0; g < 4; g++) {
            int ncol = wn * 32 + g * 8 + (lane & 3) * 2;
            stg[(mrow    ) * 132 + ncol    ] = acc[f][g][0];
            stg[(mrow    ) * 132 + ncol + 1] = acc[f][g][1];
            stg[(mrow + 8) * 132 + ncol    ] = acc[f][g][2];
            stg[(mrow + 8) * 132 + ncol + 1] = acc[f][g][3];
        }
    }
    __syncthreads();

#pragma unroll
    for (int r = 0; r < 16; r++) {
        int e = tid + 256 * r;
        int row = e >> 5, q = e & 31;
        float4 o = *(float4*)&stg[row * 132 + q * 4];
        int grow = m0 + row, gcol = n0 + q * 4;
        size_t gi = (size_t)grow * N + gcol;

        if (EPI == 2) {
            float4 rr = *(const float4*)(res + gi);
            o.x += rr.x; o.y += rr.y; o.z += rr.z; o.w += rr.w;
            *(float4*)(C + gi) = o;
        } else if (EPI == 3) {
            float4 bb = *(const float4*)(bias + gcol);
            o.x = gelu_t(o.x + bb.x); o.y = gelu_t(o.y + bb.y);
            o.z = gelu_t(o.z + bb.z); o.w = gelu_t(o.w + bb.w);
            *(uint2*)(Ch + gi) = make_uint2(pkh(o.x, o.y), pkh(o.z, o.w));
        } else if (EPI == 4) {
            float4 bb = *(const float4*)(bias + gcol);
            float4 rr = *(const float4*)(res + gi);
            o.x += bb.x + rr.x; o.y += bb.y + rr.y;
            o.z += bb.z + rr.z; o.w += bb.w + rr.w;
            *(float4*)(C + gi) = o;
        } else {  // EPI == 5: fused QKV
            int seg = gcol >> 10;
            int cin = gcol & 1023;
            float* dst = (seg == 0) ? C : (seg == 1) ? C2 : C3;
            if (seg < 2) {
                o.x = fmaxf(o.x, 0.f) + 1e-3f;
                o.y = fmaxf(o.y, 0.f) + 1e-3f;
                o.z = fmaxf(o.z, 0.f) + 1e-3f;
                o.w = fmaxf(o.w, 0.f) + 1e-3f;
            }
            *(float4*)(dst + (size_t)grow * DD + cin) = o;
        }
    }
}

// ---------------- attention pass A: per-chunk KV = phiK^T V and ksum ----------------
__global__ void __launch_bounds__(256)
attn_chunk_kernel(const float* __restrict__ Kk, const float* __restrict__ V,
                  float* __restrict__ ckv, float* __restrict__ cks)
{
    __shared__ float sK[64][64];
    __shared__ float sV[64][64];
    int g = blockIdx.x;
    int c = g & 15, bh = g >> 4;
    int h = bh & 15, b = bh >> 4;
    int row0 = b * SS + c * CCH;
    int colBase = h * 64;
    int t = threadIdx.x;
    int m = t >> 2;
    int d0 = (t & 3) * 16;

    float acc[16];
#pragma unroll
    for (int w = 0; w < 16; w++) acc[w] = 0.f;
    float ks = 0.f;

    for (int half = 0; half < 2; ++half) {
#pragma unroll
        for (int r = 0; r < 16; r++) {
            int e = t + 256 * r;
            int s = e >> 6, d = e & 63;
            size_t gi = (size_t)(row0 + half * 64 + s) * DD + colBase + d;
            sK[s][d] = Kk[gi];
            sV[s][d] = V[gi];
        }
        __syncthreads();
        for (int s = 0; s < 64; s++) {
            float kk = sK[s][m];
            if ((t & 3) == 0) ks += kk;
            const float* vr = &sV[s][d0];
#pragma unroll
            for (int w = 0; w < 4; w++) {
                float4 vv = *(const float4*)(vr + 4 * w);
                acc[4 * w + 0] += kk * vv.x;
                acc[4 * w + 1] += kk * vv.y;
                acc[4 * w + 2] += kk * vv.z;
                acc[4 * w + 3] += kk * vv.w;
            }
        }
        __syncthreads();
    }
    float* op = ckv + (size_t)g * (DHH * DHH) + m * 64 + d0;
#pragma unroll
    for (int w = 0; w < 4; w++)
        *(float4*)(op + 4 * w) = make_float4(acc[4*w], acc[4*w+1], acc[4*w+2], acc[4*w+3]);
    if ((t & 3) == 0) cks[g * 64 + m] = ks;
}

// ---------------- attention pass B: parallel exclusive prefix (gather form) ----------------
__global__ void __launch_bounds__(256)
attn_pre_kernel(const float* __restrict__ ckv, const float* __restrict__ cks,
                float* __restrict__ kvpre, float* __restrict__ kspre)
{
    int g = blockIdx.x;
    int c = g & 15, bh = g >> 4;
    int t = threadIdx.x;
    float run[16];
#pragma unroll
    for (int r = 0; r < 16; r++) run[r] = 0.f;
    for (int cc = 0; cc < c; cc++) {
        const float* p = ckv + ((size_t)(bh * NCH + cc)) * (DHH * DHH);
#pragma unroll
        for (int r = 0; r < 16; r++) run[r] += p[t + 256 * r];
    }
    float* o = kvpre + (size_t)g * (DHH * DHH);
#pragma unroll
    for (int r = 0; r < 16; r++) o[t + 256 * r] = run[r];
    if (t < 64) {
        float kr = 0.f;
        for (int cc = 0; cc < c; cc++) kr += cks[(bh * NCH + cc) * 64 + t];
        kspre[g * 64 + t] = kr;
    }
}

// ---------------- attention pass C: per-chunk causal output -> single fp16 ----------------
#define ATTN_SMEM_FLOATS (64*132 + 64*132 + 128*68 + 64*68 + 64 + 128*132)
#define ATTN_SMEM_BYTES  (ATTN_SMEM_FLOATS * 4)

__global__ void __launch_bounds__(256)
attn_out_kernel(const float* __restrict__ Q, const float* __restrict__ Kk,
                const float* __restrict__ V, const float* __restrict__ kvpre,
                const float* __restrict__ kspre, h16* __restrict__ ah)
{
    extern __shared__ float sm[];
    float* sQt = sm;
    float* sKt = sQt + 64 * 132;
    float* sV  = sKt + 64 * 132;
    float* sKV = sV  + 128 * 68;
    float* sKs = sKV + 64 * 68;
    float* sA  = sKs + 64;

    int g = blockIdx.x;
    int c = g & 15, bh = g >> 4;
    int h = bh & 15, b = bh >> 4;
    int row0 = b * SS + c * CCH;
    int colBase = h * 64;
    int t = threadIdx.x;

#pragma unroll
    for (int r = 0; r < 32; r++) {
        int e = t + 256 * r;
        int s = e >> 6, m = e & 63;
        size_t gi = (size_t)(row0 + s) * DD + colBase + m;
        sQt[m * 132 + s] = Q[gi];
        sKt[m * 132 + s] = Kk[gi];
        sV[s * 68 + m]   = V[gi];
    }
#pragma unroll
    for (int r = 0; r < 16; r++) {
        int e = t + 256 * r;
        sKV[(e >> 6) * 68 + (e & 63)] = kvpre[(size_t)g * (DHH * DHH) + e];
    }
    if (t < 64) sKs[t] = kspre[g * 64 + t];
    __syncthreads();

    {
        int ty = t >> 4, tx = t & 15;
        float accA[8][8];
#pragma unroll
        for (int i = 0; i < 8; i++)
#pragma unroll
            for (int j = 0; j < 8; j++) accA[i][j] = 0.f;
        for (int kk = 0; kk < 64; kk++) {
            const float* qr = &sQt[kk * 132 + ty * 8];
            float4 q0 = *(const float4*)qr;
            float4 q1 = *(const float4*)(qr + 4);
            const float* kr = &sKt[kk * 132 + tx * 8];
            float4 k0 = *(const float4*)kr;
            float4 k1 = *(const float4*)(kr + 4);
            float qa[8] = { q0.x, q0.y, q0.z, q0.w, q1.x, q1.y, q1.z, q1.w };
            float kb[8] = { k0.x, k0.y, k0.z, k0.w, k1.x, k1.y, k1.z, k1.w };
#pragma unroll
            for (int i = 0; i < 8; i++)
#pragma unroll
                for (int j = 0; j < 8; j++) accA[i][j] += qa[i] * kb[j];
        }
        int i0 = ty * 8, j0 = tx * 8;
#pragma unroll
        for (int i = 0; i < 8; i++)
#pragma unroll
            for (int j = 0; j < 8; j++)
                sA[(i0 + i) * 132 + (j0 + j)] = (j0 + j <= i0 + i) ? accA[i][j] : 0.f;
    }
    __syncthreads();

    {
        int i = t >> 1;
        int d0 = (t & 1) * 32;
        float acc[32];
#pragma unroll
        for (int w = 0; w < 32; w++) acc[w] = 0.f;
        float den = 0.f;
        for (int j = 0; j < 128; j++) {
            float a = sA[i * 132 + j];
            den += a;
            const float* vr = &sV[j * 68 + d0];
#pragma unroll
            for (int w = 0; w < 8; w++) {
                float4 vv = *(const float4*)(vr + 4 * w);
                acc[4 * w + 0] += a * vv.x;
                acc[4 * w + 1] += a * vv.y;
                acc[4 * w + 2] += a * vv.z;
                acc[4 * w + 3] += a * vv.w;
            }
        }
        for (int m = 0; m < 64; m++) {
            float p = sQt[m * 132 + i];
            den += p * sKs[m];
            const float* kr = &sKV[m * 68 + d0];
#pragma unroll
            for (int w = 0; w < 8; w++) {
                float4 vv = *(const float4*)(kr + 4 * w);
                acc[4 * w + 0] += p * vv.x;
                acc[4 * w + 1] += p * vv.y;
                acc[4 * w + 2] += p * vv.z;
                acc[4 * w + 3] += p * vv.w;
            }
        }
        float inv = 1.0f / den;
        size_t base = (size_t)(row0 + i) * DD + colBase + d0;
#pragma unroll
        for (int w = 0; w < 8; w++) {
            float o0 = acc[4*w+0] * inv, o1 = acc[4*w+1] * inv;
            float o2 = acc[4*w+2] * inv, o3 = acc[4*w+3] * inv;
            *(uint2*)(ah + base + 4 * w) = make_uint2(pkh(o0, o1), pkh(o2, o3));
        }
    }
}

// ---------------- launch ----------------
extern "C" void kernel_launch(void* const* d_in, const int* in_sizes, int n_in,
                              void* d_out, int out_size)
{
    const float* inputs = (const float*)d_in[0];
    const float* ln1s   = (const float*)d_in[1];
    const float* ln1b   = (const float*)d_in[2];
    const float* wq     = (const float*)d_in[3];
    const float* wk     = (const float*)d_in[4];
    const float* wv     = (const float*)d_in[5];
    const float* wo     = (const float*)d_in[6];
    const float* ln2s   = (const float*)d_in[7];
    const float* ln2b   = (const float*)d_in[8];
    const float* w1     = (const float*)d_in[9];
    const float* b1     = (const float*)d_in[10];
    const float* w2     = (const float*)d_in[11];
    const float* b2     = (const float*)d_in[12];
    float* out = (float*)d_out;

    float *q, *k, *v, *x2, *ckv, *cks, *kvpre, *kspre;
    h16 *xh, *ah, *yh, *h1h;
    h16 *wqkvt, *wot, *w1t, *w2t;
    cudaGetSymbolAddress((void**)&q,     g_q);
    cudaGetSymbolAddress((void**)&k,     g_k);
    cudaGetSymbolAddress((void**)&v,     g_v);
    cudaGetSymbolAddress((void**)&x2,    g_x2);
    cudaGetSymbolAddress((void**)&ckv,   g_ckv);
    cudaGetSymbolAddress((void**)&cks,   g_cks);
    cudaGetSymbolAddress((void**)&kvpre, g_kvpre);
    cudaGetSymbolAddress((void**)&kspre, g_kspre);
    cudaGetSymbolAddress((void**)&xh,  g_xh);
    cudaGetSymbolAddress((void**)&ah,  g_ah);
    cudaGetSymbolAddress((void**)&yh,  g_yh);
    cudaGetSymbolAddress((void**)&h1h, g_h1h);
    cudaGetSymbolAddress((void**)&wqkvt, g_wqkvt);
    cudaGetSymbolAddress((void**)&wot, g_wot);
    cudaGetSymbolAddress((void**)&w1t, g_w1t);
    cudaGetSymbolAddress((void**)&w2t, g_w2t);

    cudaFuncSetAttribute(attn_out_kernel,
                         cudaFuncAttributeMaxDynamicSharedMemorySize, ATTN_SMEM_BYTES);
    cudaFuncSetAttribute(mma_gemm<2>, cudaFuncAttributeMaxDynamicSharedMemorySize, GEMM_SMEM_BYTES);
    cudaFuncSetAttribute(mma_gemm<3>, cudaFuncAttributeMaxDynamicSharedMemorySize, GEMM_SMEM_BYTES);
    cudaFuncSetAttribute(mma_gemm<4>, cudaFuncAttributeMaxDynamicSharedMemorySize, GEMM_SMEM_BYTES);
    cudaFuncSetAttribute(mma_gemm<5>, cudaFuncAttributeMaxDynamicSharedMemorySize, GEMM_SMEM_BYTES);

    // 0) fused weight transpose + fp16 convert (one launch for all 6 weights)
    wsplit_all<<<12288, 256>>>(wq, wk, wv, wo, w1, w2);

    // 1) LN1 -> fp16
    ln_kernel<<<ROWS, 256>>>(inputs, ln1s, ln1b, xh);

    // 2) fused QKV projection (phi fused for q,k segments; v plain)
    mma_gemm<5><<<dim3(3 * DD / 128, ROWS / 128), 256, GEMM_SMEM_BYTES>>>(
        xh, wqkvt, q, k, v, nullptr, nullptr, nullptr, ROWS, 3 * DD, DD);

    // 3) chunked causal linear attention
    attn_chunk_kernel<<<NCHUNKS_TOT, 256>>>(k, v, ckv, cks);
    attn_pre_kernel<<<NCHUNKS_TOT, 256>>>(ckv, cks, kvpre, kspre);
    attn_out_kernel<<<NCHUNKS_TOT, 256, ATTN_SMEM_BYTES>>>(q, k, v, kvpre, kspre, ah);

    // 4) output projection + residual -> x2
    mma_gemm<2><<<dim3(DD / 128, ROWS / 128), 256, GEMM_SMEM_BYTES>>>(
        ah, wot, x2, nullptr, nullptr, nullptr, nullptr, inputs, ROWS, DD, DD);

    // 5) LN2 -> fp16
    ln_kernel<<<ROWS, 256>>>(x2, ln2s, ln2b, yh);

    // 6) MLP
    mma_gemm<3><<<dim3(MLPD / 128, ROWS / 128), 256, GEMM_SMEM_BYTES>>>(
        yh, w1t, nullptr, nullptr, nullptr, h1h, b1, nullptr, ROWS, MLPD, DD);
    mma_gemm<4><<<dim3(DD / 128, ROWS / 128), 256, GEMM_SMEM_BYTES>>>(
        h1h, w2t, out, nullptr, nullptr, nullptr, b2, x2, ROWS, DD, MLPD);
}

// round 17
// speedup vs baseline: 2.6083x; 1.3853x over previous
#include <cuda_runtime.h>
#include <cuda_fp16.h>
#include <math.h>
#include <stdint.h>

// ---------------- problem constants ----------------
#define BB   2
#define SS   2048
#define DD   1024
#define HH   16
#define DHH  64
#define MLPD 4096
#define ROWS (BB*SS)
#define CCH  128
#define NCH  (SS/CCH)
#define BHN  (BB*HH)
#define NCHUNKS_TOT (BHN*NCH) // 512

typedef __half h16;

// ---------------- scratch ----------------
__device__ float g_x2  [ROWS*DD];
__device__ h16 g_xh [ROWS*DD];
__device__ h16 g_qh [ROWS*DD];
__device__ h16 g_kh [ROWS*DD];
__device__ h16 g_vh [ROWS*DD];
__device__ h16 g_ah [ROWS*DD];
__device__ h16 g_yh [ROWS*DD];
__device__ h16 g_h1h[ROWS*MLPD];
__device__ h16 g_wqkvt[3*DD*DD];
__device__ h16 g_wot[DD*DD];
__device__ h16 g_w1t[DD*MLPD];
__device__ h16 g_w2t[MLPD*DD];
__device__ float g_ckv  [NCHUNKS_TOT*DHH*DHH];
__device__ float g_cks  [NCHUNKS_TOT*DHH];
__device__ float g_kvpre[NCHUNKS_TOT*DHH*DHH];
__device__ float g_kspre[NCHUNKS_TOT*DHH];

// ---------------- helpers ----------------
__device__ __forceinline__ float gelu_t(float x) {
    float x3 = x * x * x;
    float t = tanhf(0.7978845608028654f * (x + 0.044715f * x3));
    return 0.5f * x * (1.0f + t);
}
__device__ __forceinline__ unsigned pkh(float a, float b) {
    __half2 t = __floats2half2_rn(a, b);
    return *reinterpret_cast<unsigned*>(&t);
}
__device__ __forceinline__ uint32_t s2u(const void* p) {
    return (uint32_t)__cvta_generic_to_shared(p);
}
__device__ __forceinline__ void cpa16(uint32_t s, const void* g) {
    asm volatile("cp.async.cg.shared.global [%0], [%1], 16;" :: "r"(s), "l"(g));
}
#define CPA_COMMIT() asm volatile("cp.async.commit_group;" ::: "memory")
#define CPA_WAIT0()  asm volatile("cp.async.wait_group 0;" ::: "memory")

__device__ __forceinline__ void ldsm4(uint32_t& r0, uint32_t& r1, uint32_t& r2,
                                      uint32_t& r3, uint32_t a) {
    asm volatile("ldmatrix.sync.aligned.m8n8.x4.shared.b16 {%0,%1,%2,%3}, [%4];"
                 : "=r"(r0), "=r"(r1), "=r"(r2), "=r"(r3) : "r"(a));
}
__device__ __forceinline__ void ldsm2(uint32_t& r0, uint32_t& r1, uint32_t a) {
    asm volatile("ldmatrix.sync.aligned.m8n8.x2.shared.b16 {%0,%1}, [%2];"
                 : "=r"(r0), "=r"(r1) : "r"(a));
}
__device__ __forceinline__ void hmma(float* c, const uint32_t* a, const uint32_t* b) {
    asm volatile(
        "mma.sync.aligned.m16n8k16.row.col.f32.f16.f16.f32 "
        "{%0,%1,%2,%3}, {%4,%5,%6,%7}, {%8,%9}, {%0,%1,%2,%3};"
        : "+f"(c[0]), "+f"(c[1]), "+f"(c[2]), "+f"(c[3])
        : "r"(a[0]), "r"(a[1]), "r"(a[2]), "r"(a[3]), "r"(b[0]), "r"(b[1]));
}

// ---------------- fused weight transpose + fp16 convert ----------------
__global__ void __launch_bounds__(256)
wsplit_all(const float* __restrict__ wq, const float* __restrict__ wk,
           const float* __restrict__ wv, const float* __restrict__ wo,
           const float* __restrict__ w1, const float* __restrict__ w2)
{
    int id = blockIdx.x;
    const float* W;
    h16 *Th;
    int K, N, n0, k0;
    if (id < 3072) {
        int w = id >> 10, tile = id & 1023;
        W = (w == 0) ? wq : (w == 1) ? wk : wv;
        K = DD; N = DD;
        Th = g_wqkvt + (size_t)w * DD * DD;
        n0 = (tile & 31) * 32; k0 = (tile >> 5) * 32;
    } else if (id < 4096) {
        int tile = id - 3072;
        W = wo; K = DD; N = DD;
        Th = g_wot;
        n0 = (tile & 31) * 32; k0 = (tile >> 5) * 32;
    } else if (id < 8192) {
        int tile = id - 4096;
        W = w1; K = DD; N = MLPD;
        Th = g_w1t;
        n0 = (tile & 127) * 32; k0 = (tile >> 7) * 32;
    } else {
        int tile = id - 8192;
        W = w2; K = MLPD; N = DD;
        Th = g_w2t;
        n0 = (tile & 31) * 32; k0 = (tile >> 5) * 32;
    }

    __shared__ float t[32][33];
    int tx = threadIdx.x & 31, ty = threadIdx.x >> 5;
#pragma unroll
    for (int r = 0; r < 4; r++) {
        int k = k0 + ty + r * 8;
        t[ty + r * 8][tx] = W[(size_t)k * N + n0 + tx];
    }
    __syncthreads();
#pragma unroll
    for (int r = 0; r < 4; r++) {
        int n = n0 + ty + r * 8;
        Th[(size_t)n * K + k0 + tx] = __float2half_rn(t[tx][ty + r * 8]);
    }
}

// ---------------- LayerNorm -> fp16 ----------------
__global__ void __launch_bounds__(256)
ln_kernel(const float* __restrict__ x, const float* __restrict__ sc,
          const float* __restrict__ bi, h16* __restrict__ yh)
{
    int row = blockIdx.x;
    int t = threadIdx.x;
    const float4* xr = (const float4*)(x + (size_t)row * DD);
    float4 v = xr[t];
    float s  = v.x + v.y + v.z + v.w;
    float ss = v.x*v.x + v.y*v.y + v.z*v.z + v.w*v.w;
#pragma unroll
    for (int o = 16; o > 0; o >>= 1) {
        s  += __shfl_xor_sync(0xffffffffu, s,  o);
        ss += __shfl_xor_sync(0xffffffffu, ss, o);
    }
    __shared__ float sh[16];
    int w = t >> 5, l = t & 31;
    if (l == 0) { sh[w] = s; sh[8 + w] = ss; }
    __syncthreads();
    if (t < 32) {
        s  = (t < 8) ? sh[t]     : 0.f;
        ss = (t < 8) ? sh[8 + t] : 0.f;
#pragma unroll
        for (int o = 4; o > 0; o >>= 1) {
            s  += __shfl_xor_sync(0xffffffffu, s,  o);
            ss += __shfl_xor_sync(0xffffffffu, ss, o);
        }
        if (t == 0) { sh[0] = s; sh[8] = ss; }
    }
    __syncthreads();
    float mean = sh[0] * (1.0f / (float)DD);
    float var  = sh[8] * (1.0f / (float)DD) - mean * mean;
    float rs = rsqrtf(var + 1e-6f);
    float4 scv = ((const float4*)sc)[t];
    float4 biv = ((const float4*)bi)[t];
    float o0 = (v.x - mean) * rs * scv.x + biv.x;
    float o1 = (v.y - mean) * rs * scv.y + biv.y;
    float o2 = (v.z - mean) * rs * scv.z + biv.z;
    float o3 = (v.w - mean) * rs * scv.w + biv.w;
    *(uint2*)(yh + (size_t)row * DD + t * 4) =
        make_uint2(pkh(o0, o1), pkh(o2, o3));
}

// ---------------- mma.sync plain fp16 GEMM ----------------
// EPI: 2 +res fp32 ; 3 +bias gelu -> fp16 ; 4 +bias +res fp32 ;
//      5 fused QKV -> fp16 q/k/v (seg 0,1 relu+eps ; 2 plain)
#define BKK        32
#define ROWSTRIDE  40
#define MAT_B      (128*ROWSTRIDE*2)
#define STAGE_B    (2*MAT_B)
#define GEMM_SMEM_BYTES (128*132*4)

template <int EPI>
__global__ void __launch_bounds__(256, 2)
mma_gemm(const h16* __restrict__ A, const h16* __restrict__ B,
         float* __restrict__ C,
         h16* __restrict__ Ch, h16* __restrict__ Ch2, h16* __restrict__ Ch3,
         const float* __restrict__ bias, const float* __restrict__ res,
         int M, int N, int K)
{
    extern __shared__ h16 smbuf[];
    uint32_t sb = s2u(smbuf);
    int tid = threadIdx.x, lane = tid & 31, wid = tid >> 5;
    int wm = wid >> 2, wn = wid & 3;
    int m0 = blockIdx.y * 128, n0 = blockIdx.x * 128;

    float acc[4][4][4];
#pragma unroll
    for (int f = 0; f < 4; f++)
#pragma unroll
        for (int g = 0; g < 4; g++)
#pragma unroll
            for (int e = 0; e < 4; e++) acc[f][g][e] = 0.f;

    auto load_stage = [&](int kt, int st) {
        int koff = kt * BKK;
        uint32_t s0 = sb + (uint32_t)st * STAGE_B;
#pragma unroll
        for (int r = 0; r < 2; r++) {
            int e = tid + 256 * r;
            int row = e >> 2, q = e & 3;
            uint32_t so = (uint32_t)(row * ROWSTRIDE + q * 8) * 2;
            size_t ga = (size_t)(m0 + row) * K + koff + q * 8;
            size_t gb = (size_t)(n0 + row) * K + koff + q * 8;
            cpa16(s0 +         so, A + ga);
            cpa16(s0 + MAT_B + so, B + gb);
        }
    };

    load_stage(0, 0);
    CPA_COMMIT();
    CPA_WAIT0();
    __syncthreads();

    const int KT = K / BKK;
    for (int kt = 0; kt < KT; ++kt) {
        int st = kt & 1;
        if (kt + 1 < KT) { load_stage(kt + 1, st ^ 1); CPA_COMMIT(); }

        uint32_t sA = sb + (uint32_t)st * STAGE_B;
        uint32_t sB = sA + MAT_B;
#pragma unroll
        for (int ks = 0; ks < 2; ++ks) {
            int kb = ks * 16;
            uint32_t ar[4][4], br[4][2];
#pragma unroll
            for (int f = 0; f < 4; f++) {
                int row = wm * 64 + f * 16 + (lane & 7) + ((lane >> 3) & 1) * 8;
                int col = kb + ((lane >> 4) << 3);
                uint32_t ad = sA + (uint32_t)(row * ROWSTRIDE + col) * 2;
                ldsm4(ar[f][0], ar[f][1], ar[f][2], ar[f][3], ad);
            }
#pragma unroll
            for (int g = 0; g < 4; g++) {
                int l2 = lane & 15;
                int nrow = wn * 32 + g * 8 + (l2 & 7);
                int col = kb + ((l2 >> 3) << 3);
                uint32_t bd = sB + (uint32_t)(nrow * ROWSTRIDE + col) * 2;
                ldsm2(br[g][0], br[g][1], bd);
            }
#pragma unroll
            for (int f = 0; f < 4; f++)
#pragma unroll
                for (int g = 0; g < 4; g++) hmma(acc[f][g], ar[f], br[g]);
        }
        if (kt + 1 < KT) CPA_WAIT0();
        __syncthreads();
    }

    float* stg = (float*)smbuf;
#pragma unroll
    for (int f = 0; f < 4; f++) {
        int mrow = wm * 64 + f * 16 + (lane >> 2);
#pragma unroll
        for (int g = 0; g < 4; g++) {
            int ncol = wn * 32 + g * 8 + (lane & 3) * 2;
            stg[(mrow    ) * 132 + ncol    ] = acc[f][g][0];
            stg[(mrow    ) * 132 + ncol + 1] = acc[f][g][1];
            stg[(mrow + 8) * 132 + ncol    ] = acc[f][g][2];
            stg[(mrow + 8) * 132 + ncol + 1] = acc[f][g][3];
        }
    }
    __syncthreads();

#pragma unroll
    for (int r = 0; r < 16; r++) {
        int e = tid + 256 * r;
        int row = e >> 5, q = e & 31;
        float4 o = *(float4*)&stg[row * 132 + q * 4];
        int grow = m0 + row, gcol = n0 + q * 4;
        size_t gi = (size_t)grow * N + gcol;

        if (EPI == 2) {
            float4 rr = *(const float4*)(res + gi);
            o.x += rr.x; o.y += rr.y; o.z += rr.z; o.w += rr.w;
            *(float4*)(C + gi) = o;
        } else if (EPI == 3) {
            float4 bb = *(const float4*)(bias + gcol);
            o.x = gelu_t(o.x + bb.x); o.y = gelu_t(o.y + bb.y);
            o.z = gelu_t(o.z + bb.z); o.w = gelu_t(o.w + bb.w);
            *(uint2*)(Ch + gi) = make_uint2(pkh(o.x, o.y), pkh(o.z, o.w));
        } else if (EPI == 4) {
            float4 bb = *(const float4*)(bias + gcol);
            float4 rr = *(const float4*)(res + gi);
            o.x += bb.x + rr.x; o.y += bb.y + rr.y;
            o.z += bb.z + rr.z; o.w += bb.w + rr.w;
            *(float4*)(C + gi) = o;
        } else {  // EPI == 5: fused QKV -> fp16
            int seg = gcol >> 10;
            int cin = gcol & 1023;
            h16* dst = (seg == 0) ? Ch : (seg == 1) ? Ch2 : Ch3;
            if (seg < 2) {
                o.x = fmaxf(o.x, 0.f) + 1e-3f;
                o.y = fmaxf(o.y, 0.f) + 1e-3f;
                o.z = fmaxf(o.z, 0.f) + 1e-3f;
                o.w = fmaxf(o.w, 0.f) + 1e-3f;
            }
            *(uint2*)(dst + (size_t)grow * DD + cin) =
                make_uint2(pkh(o.x, o.y), pkh(o.z, o.w));
        }
    }
}

// ---------------- attention pass A (HMMA): ckv[m][d] = sum_s phiK[s][m] V[s][d] ----------------
__global__ void __launch_bounds__(128)
attn_chunk_kernel(const h16* __restrict__ Kh, const h16* __restrict__ Vh,
                  float* __restrict__ ckv, float* __restrict__ cks)
{
    __shared__ h16 sKt[64 * 136];   // [m][s]
    __shared__ h16 sVt[64 * 136];   // [d][s]
    int g = blockIdx.x;
    int c = g & 15, bh = g >> 4;
    int h = bh & 15, b = bh >> 4;
    int row0 = b * SS + c * CCH;
    int colBase = h * 64;
    int t = threadIdx.x, lane = t & 31, w = t >> 5;

    // load + transpose: 2048 uint2 per tensor
#pragma unroll
    for (int r = 0; r < 16; r++) {
        int e = t + 128 * r;
        int s = e >> 4, m4 = (e & 15) * 4;
        size_t gi = (size_t)(row0 + s) * DD + colBase + m4;
        uint2 kk = *(const uint2*)(Kh + gi);
        uint2 vv = *(const uint2*)(Vh + gi);
        const h16* kp = (const h16*)&kk;
        const h16* vp = (const h16*)&vv;
#pragma unroll
        for (int i = 0; i < 4; i++) {
            sKt[(m4 + i) * 136 + s] = kp[i];
            sVt[(m4 + i) * 136 + s] = vp[i];
        }
    }
    __syncthreads();

    uint32_t kbase = s2u(sKt), vbase = s2u(sVt);
    float acc[8][4];
#pragma unroll
    for (int gg = 0; gg < 8; gg++)
#pragma unroll
        for (int e = 0; e < 4; e++) acc[gg][e] = 0.f;

#pragma unroll
    for (int ks = 0; ks < 8; ks++) {
        int kb = ks * 16;
        uint32_t ar[4];
        int row = w * 16 + (lane & 7) + ((lane >> 3) & 1) * 8;
        int col = kb + ((lane >> 4) << 3);
        ldsm4(ar[0], ar[1], ar[2], ar[3], kbase + (uint32_t)(row * 136 + col) * 2);
        int l2 = lane & 15;
#pragma unroll
        for (int gg = 0; gg < 8; gg++) {
            int nrow = gg * 8 + (l2 & 7);
            int coln = kb + ((l2 >> 3) << 3);
            uint32_t br[2];
            ldsm2(br[0], br[1], vbase + (uint32_t)(nrow * 136 + coln) * 2);
            hmma(acc[gg], ar, br);
        }
    }

    float* base = ckv + (size_t)g * (DHH * DHH);
    int mr = w * 16 + (lane >> 2);
    int dc = (lane & 3) * 2;
#pragma unroll
    for (int gg = 0; gg < 8; gg++) {
        int d = gg * 8 + dc;
        base[ mr      * 64 + d] = acc[gg][0];
        base[ mr      * 64 + d + 1] = acc[gg][1];
        base[(mr + 8) * 64 + d] = acc[gg][2];
        base[(mr + 8) * 64 + d + 1] = acc[gg][3];
    }
    __syncthreads();
    if (t < 64) {
        float s = 0.f;
        const __half2* rp = (const __half2*)&sKt[t * 136];
#pragma unroll
        for (int i = 0; i < 64; i++) {
            float2 f = __half22float2(rp[i]);
            s += f.x + f.y;
        }
        cks[g * 64 + t] = s;
    }
}

// ---------------- attention pass B: parallel exclusive prefix (gather) ----------------
__global__ void __launch_bounds__(256)
attn_pre_kernel(const float* __restrict__ ckv, const float* __restrict__ cks,
                float* __restrict__ kvpre, float* __restrict__ kspre)
{
    int g = blockIdx.x;
    int c = g & 15, bh = g >> 4;
    int t = threadIdx.x;
    float run[16];
#pragma unroll
    for (int r = 0; r < 16; r++) run[r] = 0.f;
    for (int cc = 0; cc < c; cc++) {
        const float* p = ckv + ((size_t)(bh * NCH + cc)) * (DHH * DHH);
#pragma unroll
        for (int r = 0; r < 16; r++) run[r] += p[t + 256 * r];
    }
    float* o = kvpre + (size_t)g * (DHH * DHH);
#pragma unroll
    for (int r = 0; r < 16; r++) o[t + 256 * r] = run[r];
    if (t < 64) {
        float kr = 0.f;
        for (int cc = 0; cc < c; cc++) kr += cks[(bh * NCH + cc) * 64 + t];
        kspre[g * 64 + t] = kr;
    }
}

// ---------------- attention pass C (HMMA) ----------------
// smem (h16 units): sQ[128*72], sK[128*72], sVt[64*136], sKVt[64*72], sAh[128*136]
// then fp32: sden[128], sksp[64]
#define AO_Q   0
#define AO_K   (128*72)
#define AO_VT  (AO_K + 128*72)
#define AO_KVT (AO_VT + 64*136)
#define AO_AH  (AO_KVT + 64*72)
#define AO_H16 (AO_AH + 128*136)
#define ATTN_SMEM_BYTES (AO_H16*2 + 128*4 + 64*4)

__global__ void __launch_bounds__(256)
attn_out_kernel(const h16* __restrict__ Qh, const h16* __restrict__ Kh,
                const h16* __restrict__ Vh, const float* __restrict__ kvpre,
                const float* __restrict__ kspre, h16* __restrict__ ah)
{
    extern __shared__ h16 sm16[];
    h16* sQ   = sm16 + AO_Q;
    h16* sK   = sm16 + AO_K;
    h16* sVt  = sm16 + AO_VT;
    h16* sKVt = sm16 + AO_KVT;
    h16* sAh  = sm16 + AO_AH;
    float* sden = (float*)(sm16 + AO_H16);
    float* sksp = sden + 128;

    int g = blockIdx.x;
    int c = g & 15, bh = g >> 4;
    int h = bh & 15, b = bh >> 4;
    int row0 = b * SS + c * CCH;
    int colBase = h * 64;
    int t = threadIdx.x, lane = t & 31, wid = t >> 5;

    // loads
#pragma unroll
    for (int r = 0; r < 8; r++) {
        int e = t + 256 * r;                 // 0..2047
        int s = e >> 4, m4 = (e & 15) * 4;
        size_t gi = (size_t)(row0 + s) * DD + colBase + m4;
        uint2 qq = *(const uint2*)(Qh + gi);
        uint2 kk = *(const uint2*)(Kh + gi);
        uint2 vv = *(const uint2*)(Vh + gi);
        *(uint2*)(sQ + s * 72 + m4) = qq;
        *(uint2*)(sK + s * 72 + m4) = kk;
        const h16* vp = (const h16*)&vv;
#pragma unroll
        for (int i = 0; i < 4; i++) sVt[(m4 + i) * 136 + s] = vp[i];
    }
#pragma unroll
    for (int r = 0; r < 16; r++) {
        int e = t + 256 * r;                 // 0..4095
        int m = e >> 6, d = e & 63;
        sKVt[d * 72 + m] = __float2half_rn(kvpre[(size_t)g * (DHH * DHH) + m * 64 + d]);
    }
    if (t < 64) sksp[t] = kspre[g * 64 + t];
    __syncthreads();

    uint32_t qb = s2u(sQ), kb_ = s2u(sK), vb = s2u(sVt), kvb = s2u(sKVt), ab = s2u(sAh);

    // phase 1: A = phiQ * phiK^T (128x128, K=64), causal mask -> sAh (fp16)
    {
        int wm = wid >> 2, wn = wid & 3;
        float acc[4][4][4];
#pragma unroll
        for (int f = 0; f < 4; f++)
#pragma unroll
            for (int gq = 0; gq < 4; gq++)
#pragma unroll
                for (int e = 0; e < 4; e++) acc[f][gq][e] = 0.f;
#pragma unroll
        for (int ks = 0; ks < 4; ks++) {
            int kk = ks * 16;
            uint32_t ar[4][4], br[4][2];
#pragma unroll
            for (int f = 0; f < 4; f++) {
                int row = wm * 64 + f * 16 + (lane & 7) + ((lane >> 3) & 1) * 8;
                int col = kk + ((lane >> 4) << 3);
                ldsm4(ar[f][0], ar[f][1], ar[f][2], ar[f][3],
                      qb + (uint32_t)(row * 72 + col) * 2);
            }
            int l2 = lane & 15;
#pragma unroll
            for (int gq = 0; gq < 4; gq++) {
                int nrow = wn * 32 + gq * 8 + (l2 & 7);
                int col = kk + ((l2 >> 3) << 3);
                ldsm2(br[gq][0], br[gq][1], kb_ + (uint32_t)(nrow * 72 + col) * 2);
            }
#pragma unroll
            for (int f = 0; f < 4; f++)
#pragma unroll
                for (int gq = 0; gq < 4; gq++) hmma(acc[f][gq], ar[f], br[gq]);
        }
        // masked fp16 write
#pragma unroll
        for (int f = 0; f < 4; f++) {
            int i0 = wm * 64 + f * 16 + (lane >> 2);
#pragma unroll
            for (int gq = 0; gq < 4; gq++) {
                int j0 = wn * 32 + gq * 8 + (lane & 3) * 2;
                sAh[ i0      * 136 + j0    ] = __float2half_rn((j0     <= i0    ) ? acc[f][gq][0] : 0.f);
                sAh[ i0      * 136 + j0 + 1] = __float2half_rn((j0 + 1 <= i0    ) ? acc[f][gq][1] : 0.f);
                sAh[(i0 + 8) * 136 + j0    ] = __float2half_rn((j0     <= i0 + 8) ? acc[f][gq][2] : 0.f);
                sAh[(i0 + 8) * 136 + j0 + 1] = __float2half_rn((j0 + 1 <= i0 + 8) ? acc[f][gq][3] : 0.f);
            }
        }
    }
    __syncthreads();

    // den rows
    if (t < 128) {
        float s = 0.f;
        const __half2* rp = (const __half2*)&sAh[t * 136];
#pragma unroll
        for (int j = 0; j < 64; j++) {
            float2 f = __half22float2(rp[j]);
            s += f.x + f.y;
        }
        const __half2* qp = (const __half2*)&sQ[t * 72];
#pragma unroll
        for (int m = 0; m < 32; m++) {
            float2 f = __half22float2(qp[m]);
            s += f.x * sksp[2 * m] + f.y * sksp[2 * m + 1];
        }
        sden[t] = s;
    }
    __syncthreads();

    // phase 2: out = A*V (K=128) + phiQ*KVpre^T (K=64), divide, store fp16
    {
        int wm = wid >> 2, wn = wid & 3;   // M=128 (2x64), N=64 (4x16)
        float acc[4][2][4];
#pragma unroll
        for (int f = 0; f < 4; f++)
#pragma unroll
            for (int gg = 0; gg < 2; gg++)
#pragma unroll
                for (int e = 0; e < 4; e++) acc[f][gg][e] = 0.f;

#pragma unroll
        for (int ks = 0; ks < 8; ks++) {
            int kk = ks * 16;
            uint32_t ar[4][4], br[2][2];
#pragma unroll
            for (int f = 0; f < 4; f++) {
                int row = wm * 64 + f * 16 + (lane & 7) + ((lane >> 3) & 1) * 8;
                int col = kk + ((lane >> 4) << 3);
                ldsm4(ar[f][0], ar[f][1], ar[f][2], ar[f][3],
                      ab + (uint32_t)(row * 136 + col) * 2);
            }
            int l2 = lane & 15;
#pragma unroll
            for (int gg = 0; gg < 2; gg++) {
                int nrow = wn * 16 + gg * 8 + (l2 & 7);
                int col = kk + ((l2 >> 3) << 3);
                ldsm2(br[gg][0], br[gg][1], vb + (uint32_t)(nrow * 136 + col) * 2);
            }
#pragma unroll
            for (int f = 0; f < 4; f++)
#pragma unroll
                for (int gg = 0; gg < 2; gg++) hmma(acc[f][gg], ar[f], br[gg]);
        }
#pragma unroll
        for (int ks = 0; ks < 4; ks++) {
            int kk = ks * 16;
            uint32_t ar[4][4], br[2][2];
#pragma unroll
            for (int f = 0; f < 4; f++) {
                int row = wm * 64 + f * 16 + (lane & 7) + ((lane >> 3) & 1) * 8;
                int col = kk + ((lane >> 4) << 3);
                ldsm4(ar[f][0], ar[f][1], ar[f][2], ar[f][3],
                      qb + (uint32_t)(row * 72 + col) * 2);
            }
            int l2 = lane & 15;
#pragma unroll
            for (int gg = 0; gg < 2; gg++) {
                int nrow = wn * 16 + gg * 8 + (l2 & 7);
                int col = kk + ((l2 >> 3) << 3);
                ldsm2(br[gg][0], br[gg][1], kvb + (uint32_t)(nrow * 72 + col) * 2);
            }
#pragma unroll
            for (int f = 0; f < 4; f++)
#pragma unroll
                for (int gg = 0; gg < 2; gg++) hmma(acc[f][gg], ar[f], br[gg]);
        }

#pragma unroll
        for (int f = 0; f < 4; f++) {
            int i0 = wm * 64 + f * 16 + (lane >> 2);
            float inv0 = 1.0f / sden[i0];
            float inv1 = 1.0f / sden[i0 + 8];
#pragma unroll
            for (int gg = 0; gg < 2; gg++) {
                int d = wn * 16 + gg * 8 + (lane & 3) * 2;
                *(uint32_t*)(ah + (size_t)(row0 + i0    ) * DD + colBase + d) =
                    pkh(acc[f][gg][0] * inv0, acc[f][gg][1] * inv0);
                *(uint32_t*)(ah + (size_t)(row0 + i0 + 8) * DD + colBase + d) =
                    pkh(acc[f][gg][2] * inv1, acc[f][gg][3] * inv1);
            }
        }
    }
}

// ---------------- launch ----------------
extern "C" void kernel_launch(void* const* d_in, const int* in_sizes, int n_in,
                              void* d_out, int out_size)
{
    const float* inputs = (const float*)d_in[0];
    const float* ln1s   = (const float*)d_in[1];
    const float* ln1b   = (const float*)d_in[2];
    const float* wq     = (const float*)d_in[3];
    const float* wk     = (const float*)d_in[4];
    const float* wv     = (const float*)d_in[5];
    const float* wo     = (const float*)d_in[6];
    const float* ln2s   = (const float*)d_in[7];
    const float* ln2b   = (const float*)d_in[8];
    const float* w1     = (const float*)d_in[9];
    const float* b1     = (const float*)d_in[10];
    const float* w2     = (const float*)d_in[11];
    const float* b2     = (const float*)d_in[12];
    float* out = (float*)d_out;

    float *x2, *ckv, *cks, *kvpre, *kspre;
    h16 *xh, *qh, *kh, *vh, *ah, *yh, *h1h;
    h16 *wqkvt, *wot, *w1t, *w2t;
    cudaGetSymbolAddress((void**)&x2,    g_x2);
    cudaGetSymbolAddress((void**)&ckv,   g_ckv);
    cudaGetSymbolAddress((void**)&cks,   g_cks);
    cudaGetSymbolAddress((void**)&kvpre, g_kvpre);
    cudaGetSymbolAddress((void**)&kspre, g_kspre);
    cudaGetSymbolAddress((void**)&xh,  g_xh);
    cudaGetSymbolAddress((void**)&qh,  g_qh);
    cudaGetSymbolAddress((void**)&kh,  g_kh);
    cudaGetSymbolAddress((void**)&vh,  g_vh);
    cudaGetSymbolAddress((void**)&ah,  g_ah);
    cudaGetSymbolAddress((void**)&yh,  g_yh);
    cudaGetSymbolAddress((void**)&h1h, g_h1h);
    cudaGetSymbolAddress((void**)&wqkvt, g_wqkvt);
    cudaGetSymbolAddress((void**)&wot, g_wot);
    cudaGetSymbolAddress((void**)&w1t, g_w1t);
    cudaGetSymbolAddress((void**)&w2t, g_w2t);

    cudaFuncSetAttribute(attn_out_kernel,
                         cudaFuncAttributeMaxDynamicSharedMemorySize, ATTN_SMEM_BYTES);
    cudaFuncSetAttribute(mma_gemm<2>, cudaFuncAttributeMaxDynamicSharedMemorySize, GEMM_SMEM_BYTES);
    cudaFuncSetAttribute(mma_gemm<3>, cudaFuncAttributeMaxDynamicSharedMemorySize, GEMM_SMEM_BYTES);
    cudaFuncSetAttribute(mma_gemm<4>, cudaFuncAttributeMaxDynamicSharedMemorySize, GEMM_SMEM_BYTES);
    cudaFuncSetAttribute(mma_gemm<5>, cudaFuncAttributeMaxDynamicSharedMemorySize, GEMM_SMEM_BYTES);

    // 0) weights -> transposed fp16
    wsplit_all<<<12288, 256>>>(wq, wk, wv, wo, w1, w2);
    // 1) LN1 -> fp16
    ln_kernel<<<ROWS, 256>>>(inputs, ln1s, ln1b, xh);
    // 2) fused QKV -> fp16 q,k,v (phi on q,k)
    mma_gemm<5><<<dim3(3 * DD / 128, ROWS / 128), 256, GEMM_SMEM_BYTES>>>(
        xh, wqkvt, nullptr, qh, kh, vh, nullptr, nullptr, ROWS, 3 * DD, DD);
    // 3) chunked causal linear attention (tensor-core)
    attn_chunk_kernel<<<NCHUNKS_TOT, 128>>>(kh, vh, ckv, cks);
    attn_pre_kernel<<<NCHUNKS_TOT, 256>>>(ckv, cks, kvpre, kspre);
    attn_out_kernel<<<NCHUNKS_TOT, 256, ATTN_SMEM_BYTES>>>(qh, kh, vh, kvpre, kspre, ah);
    // 4) output projection + residual -> x2
    mma_gemm<2><<<dim3(DD / 128, ROWS / 128), 256, GEMM_SMEM_BYTES>>>(
        ah, wot, x2, nullptr, nullptr, nullptr, nullptr, inputs, ROWS, DD, DD);
    // 5) LN2 -> fp16
    ln_kernel<<<ROWS, 256>>>(x2, ln2s, ln2b, yh);
    // 6) MLP
    mma_gemm<3><<<dim3(MLPD / 128, ROWS / 128), 256, GEMM_SMEM_BYTES>>>(
        yh, w1t, nullptr, h1h, nullptr, nullptr, b1, nullptr, ROWS, MLPD, DD);
    mma_gemm<4><<<dim3(DD / 128, ROWS / 128), 256, GEMM_SMEM_BYTES>>>(
        h1h, w2t, out, nullptr, nullptr, nullptr, b2, x2, ROWS, DD, MLPD);
}